// round 7
// baseline (speedup 1.0000x reference)
#include <cuda_runtime.h>
#include <cuda_bf16.h>
#include <mma.h>

using namespace nvcuda;

#define N_ 8192
#define D_ 128
#define NLAB 10
#define SCALE 0.08838834764831845f   // 1/sqrt(128)
#define EPS 1e-8f
#define TW 128                        // walker tile width

// ---------------- scratch (device globals: allocation-free) ----------------
static __device__ __nv_bfloat16 g_E16[(size_t)N_ * N_];  // exp(p) bf16 (128 MB)
static __device__ __nv_bfloat16 g_U[(size_t)N_ * N_];    // ab      (128 MB)
static __device__ __nv_bfloat16 g_V[(size_t)N_ * N_];    // ba^T    (128 MB)
static __device__ float g_rsum[N_];   // row sums -> inverted in place
static __device__ float g_csum[N_];   // col sums -> inverted in place
static __device__ float g_vp[N_];     // column sums of U
static __device__ int   g_cnt[NLAB];
static __device__ int   g_startL[NLAB + 1];
static __device__ int   g_idx[N_];
static __device__ int   g_tilesL[NLAB];
static __device__ int   g_tileStart[NLAB + 1];
static __device__ int   g_numTiles;
static __device__ int   g_isI64;
static __device__ float g_walkerAcc;

__device__ __forceinline__ int get_label(const void* L, int i, int isI64) {
    int v = isI64 ? (int)((const long long*)L)[i] : ((const int*)L)[i];
    return min(max(v, 0), NLAB - 1);
}

// ---------------- 0) zero the atomic accumulators ----------------
__global__ __launch_bounds__(512) void init_kernel() {
    int i = blockIdx.x * 512 + threadIdx.x;
    if (i < N_) { g_rsum[i] = 0.f; g_csum[i] = 0.f; g_vp[i] = 0.f; }
    if (i == 0) g_walkerAcc = 0.f;
}

// ---------------- 1) P = a b^T * scale; E=exp(P) bf16; fused row/col sums ----------------
__global__ __launch_bounds__(256) void gemm_p_kernel(const float* __restrict__ A,
                                                     const float* __restrict__ B) {
    __shared__ float As[32][68];
    __shared__ float Bs[32][68];
    __shared__ float rp[64][16];
    __shared__ float cp[64][16];
    int tid = threadIdx.x;
    int tx = tid & 15, ty = tid >> 4;
    int bi = blockIdx.y * 64, bj = blockIdx.x * 64;
    float acc[4][4] = {};
    for (int k0 = 0; k0 < D_; k0 += 32) {
        #pragma unroll
        for (int q = 0; q < 8; q++) {
            int l = tid + q * 256;
            int r = l >> 5, k = l & 31;
            As[k][r] = A[(size_t)(bi + r) * D_ + k0 + k];
            Bs[k][r] = B[(size_t)(bj + r) * D_ + k0 + k];
        }
        __syncthreads();
        #pragma unroll
        for (int k = 0; k < 32; k++) {
            float ra[4], rb[4];
            #pragma unroll
            for (int i = 0; i < 4; i++) ra[i] = As[k][ty * 4 + i];
            #pragma unroll
            for (int j = 0; j < 4; j++) rb[j] = Bs[k][tx * 4 + j];
            #pragma unroll
            for (int i = 0; i < 4; i++)
                #pragma unroll
                for (int j = 0; j < 4; j++) acc[i][j] += ra[i] * rb[j];
        }
        __syncthreads();
    }
    // epilogue: exp, bf16 store, fused row/col partial sums
    float colp[4] = {0.f, 0.f, 0.f, 0.f};
    #pragma unroll
    for (int i = 0; i < 4; i++) {
        float e[4], rowp = 0.f;
        #pragma unroll
        for (int j = 0; j < 4; j++) {
            e[j] = __expf(acc[i][j] * SCALE);
            rowp += e[j];
            colp[j] += e[j];
        }
        __nv_bfloat162 p0 = __floats2bfloat162_rn(e[0], e[1]);
        __nv_bfloat162 p1 = __floats2bfloat162_rn(e[2], e[3]);
        uint2 pk = make_uint2(*(unsigned*)&p0, *(unsigned*)&p1);
        *(uint2*)&g_E16[(size_t)(bi + ty * 4 + i) * N_ + bj + tx * 4] = pk;
        rp[ty * 4 + i][tx] = rowp;
    }
    #pragma unroll
    for (int j = 0; j < 4; j++) cp[tx * 4 + j][ty] = colp[j];
    __syncthreads();
    if (tid < 64) {
        float s = 0.f;
        #pragma unroll
        for (int k = 0; k < 16; k++) s += rp[tid][k];
        atomicAdd(&g_rsum[bi + tid], s);
    } else if (tid < 128) {
        int c = tid - 64;
        float s = 0.f;
        #pragma unroll
        for (int k = 0; k < 16; k++) s += cp[c][k];
        atomicAdd(&g_csum[bj + c], s);
    }
}

// ---------------- 2) invert sums in place ----------------
__global__ __launch_bounds__(512) void recip_kernel() {
    int i = blockIdx.x * 512 + threadIdx.x;
    if (i < N_) {
        g_rsum[i] = 1.f / g_rsum[i];
        g_csum[i] = 1.f / g_csum[i];
    }
}

// ---------------- 3) U, V (bf16) + visit column sums (vectorized) ----------------
__global__ __launch_bounds__(256) void uv_vp_kernel() {
    __shared__ float vps[128];
    int tid = threadIdx.x;
    int cg = tid & 15, rg = tid >> 4;
    int colBase = blockIdx.x * 128;
    int c = colBase + cg * 8;
    float cInv[8];
    #pragma unroll
    for (int k = 0; k < 8; k++) cInv[k] = g_csum[c + k];
    float vp[8] = {};
    int r0 = blockIdx.y * 1024 + rg;
    #pragma unroll 4
    for (int it = 0; it < 64; it++) {
        int r = r0 + it * 16;
        size_t off = (size_t)r * N_ + c;
        uint4 ev = *(const uint4*)&g_E16[off];
        float rInv = g_rsum[r];
        float e[8];
        {
            float2 f;
            f = __bfloat1622float2(*(__nv_bfloat162*)&ev.x); e[0] = f.x; e[1] = f.y;
            f = __bfloat1622float2(*(__nv_bfloat162*)&ev.y); e[2] = f.x; e[3] = f.y;
            f = __bfloat1622float2(*(__nv_bfloat162*)&ev.z); e[4] = f.x; e[5] = f.y;
            f = __bfloat1622float2(*(__nv_bfloat162*)&ev.w); e[6] = f.x; e[7] = f.y;
        }
        float u[8], v[8];
        #pragma unroll
        for (int k = 0; k < 8; k++) { u[k] = e[k] * rInv; v[k] = e[k] * cInv[k]; vp[k] += u[k]; }
        uint4 up, vv;
        __nv_bfloat162 t;
        t = __floats2bfloat162_rn(u[0], u[1]); up.x = *(unsigned*)&t;
        t = __floats2bfloat162_rn(u[2], u[3]); up.y = *(unsigned*)&t;
        t = __floats2bfloat162_rn(u[4], u[5]); up.z = *(unsigned*)&t;
        t = __floats2bfloat162_rn(u[6], u[7]); up.w = *(unsigned*)&t;
        t = __floats2bfloat162_rn(v[0], v[1]); vv.x = *(unsigned*)&t;
        t = __floats2bfloat162_rn(v[2], v[3]); vv.y = *(unsigned*)&t;
        t = __floats2bfloat162_rn(v[4], v[5]); vv.z = *(unsigned*)&t;
        t = __floats2bfloat162_rn(v[6], v[7]); vv.w = *(unsigned*)&t;
        *(uint4*)&g_U[off] = up;
        *(uint4*)&g_V[off] = vv;
    }
    if (tid < 128) vps[tid] = 0.f;
    __syncthreads();
    #pragma unroll
    for (int k = 0; k < 8; k++) atomicAdd(&vps[cg * 8 + k], vp[k]);
    __syncthreads();
    if (tid < 128) atomicAdd(&g_vp[colBase + tid], vps[tid]);
}

// ---------------- 4) dtype probe + label histogram + tile bookkeeping ----------------
__global__ __launch_bounds__(256) void prep1_kernel(const void* __restrict__ labels) {
    __shared__ int scnt[NLAB];
    __shared__ int oddNonzero;
    int tid = threadIdx.x;
    if (tid < NLAB) scnt[tid] = 0;
    if (tid == 0) oddNonzero = 0;
    __syncthreads();
    {
        const int* w = (const int*)labels;
        int local = 0;
        for (int i = tid; i < N_ / 2; i += 256)
            if (w[2 * i + 1] != 0) local = 1;
        if (local) oddNonzero = 1;
    }
    __syncthreads();
    int isI64 = !oddNonzero;
    if (tid == 0) g_isI64 = isI64;

    for (int i = tid; i < N_; i += 256)
        atomicAdd(&scnt[get_label(labels, i, isI64)], 1);
    __syncthreads();
    if (tid == 0) {
        int st = 0, ts = 0;
        for (int l = 0; l < NLAB; l++) {
            int cnum = scnt[l];
            g_cnt[l] = cnum;
            g_startL[l] = st; st += cnum;
            int tl = (cnum + TW - 1) / TW;
            g_tilesL[l] = tl;
            g_tileStart[l] = ts; ts += tl * tl;
        }
        g_startL[NLAB] = st;
        g_tileStart[NLAB] = ts;
        g_numTiles = ts;
    }
}

// ---------------- 5) deterministic stable scatter of indices by label ----------------
__global__ __launch_bounds__(256) void prep2_kernel(const void* __restrict__ labels) {
    __shared__ unsigned char slab[N_];
    int tid = threadIdx.x;
    int isI64 = g_isI64;
    for (int i = tid; i < N_; i += 256)
        slab[i] = (unsigned char)get_label(labels, i, isI64);
    __syncthreads();
    int i = blockIdx.x * 256 + tid;
    unsigned char lab = slab[i];
    int pos = 0;
    for (int q = 0; q < i; q++) pos += (slab[q] == lab);
    g_idx[g_startL[lab] + pos] = i;
}

// ---------------- 6) label-sparse aba GEMM (128x128 bf16 wmma) + log reduce ----------------
__global__ __launch_bounds__(256) void walker_kernel() {
    __shared__ __align__(32) __nv_bfloat16 Us[TW * 72];
    __shared__ __align__(32) __nv_bfloat16 Vs[TW * 72];
    __shared__ int Ridx[TW], Cidx[TW];
    __shared__ __align__(32) float wscr[8][256];
    __shared__ float red[8];

    int tid = threadIdx.x;
    int warp = tid >> 5, lane = tid & 31;
    int wr = warp >> 1;        // 0..3 : 32-row band
    int wc = warp & 1;         // 0..1 : 64-col band
    int numTiles = g_numTiles;
    float blockAcc = 0.f;

    for (int t = blockIdx.x; t < numTiles; t += gridDim.x) {
        int L = 0;
        while (t >= g_tileStart[L + 1]) L++;
        int local = t - g_tileStart[L];
        int tl = g_tilesL[L];
        int nL = g_cnt[L];
        int base = g_startL[L];
        int ti = local / tl, tj = local % tl;

        if (tid < TW) {
            int r = ti * TW + tid;
            Ridx[tid] = (r < nL) ? g_idx[base + r] : -1;
            int c = tj * TW + tid;
            Cidx[tid] = (c < nL) ? g_idx[base + c] : -1;
        }
        wmma::fragment<wmma::accumulator, 16, 16, 16, float> cf[2][4];
        #pragma unroll
        for (int i = 0; i < 2; i++)
            #pragma unroll
            for (int j = 0; j < 4; j++) wmma::fill_fragment(cf[i][j], 0.f);
        __syncthreads();

        for (int k0 = 0; k0 < N_; k0 += 64) {
            #pragma unroll
            for (int q = 0; q < 4; q++) {
                int e = tid + q * 256;
                int r = e >> 3, kk = (e & 7) * 8;
                uint4 z = make_uint4(0, 0, 0, 0);
                int gi = Ridx[r];
                uint4 vu = z;
                if (gi >= 0) vu = *(const uint4*)&g_U[(size_t)gi * N_ + k0 + kk];
                *(uint4*)&Us[r * 72 + kk] = vu;
                int gj = Cidx[r];
                uint4 vv = z;
                if (gj >= 0) vv = *(const uint4*)&g_V[(size_t)gj * N_ + k0 + kk];
                *(uint4*)&Vs[r * 72 + kk] = vv;
            }
            __syncthreads();
            #pragma unroll
            for (int ks = 0; ks < 4; ks++) {
                wmma::fragment<wmma::matrix_a, 16, 16, 16, __nv_bfloat16, wmma::row_major> a0, a1;
                wmma::load_matrix_sync(a0, &Us[(wr * 32) * 72 + ks * 16], 72);
                wmma::load_matrix_sync(a1, &Us[(wr * 32 + 16) * 72 + ks * 16], 72);
                #pragma unroll
                for (int j = 0; j < 4; j++) {
                    wmma::fragment<wmma::matrix_b, 16, 16, 16, __nv_bfloat16, wmma::col_major> b;
                    wmma::load_matrix_sync(b, &Vs[(wc * 64 + j * 16) * 72 + ks * 16], 72);
                    wmma::mma_sync(cf[0][j], a0, b, cf[0][j]);
                    wmma::mma_sync(cf[1][j], a1, b, cf[1][j]);
                }
            }
            __syncthreads();
        }

        // per-warp fragment-local log reduce (no block syncs needed)
        int rlim = nL - ti * TW;
        int clim = nL - tj * TW;
        float s = 0.f;
        #pragma unroll
        for (int i2 = 0; i2 < 2; i2++)
            #pragma unroll
            for (int j4 = 0; j4 < 4; j4++) {
                wmma::store_matrix_sync(&wscr[warp][0], cf[i2][j4], 16, wmma::mem_row_major);
                __syncwarp();
                #pragma unroll
                for (int q = 0; q < 8; q++) {
                    int idx = lane + q * 32;
                    int lr = wr * 32 + i2 * 16 + (idx >> 4);
                    int lc = wc * 64 + j4 * 16 + (idx & 15);
                    if (lr < rlim && lc < clim) s += logf(EPS + wscr[warp][idx]);
                }
                __syncwarp();
            }
        #pragma unroll
        for (int o = 16; o; o >>= 1) s += __shfl_xor_sync(~0u, s, o);
        if (lane == 0) red[warp] = s;
        __syncthreads();
        if (tid == 0) {
            float ts = 0.f;
            for (int w = 0; w < 8; w++) ts += red[w];
            blockAcc += ts / (float)nL;
        }
        __syncthreads();
    }
    if (tid == 0) atomicAdd(&g_walkerAcc, blockAcc);
}

// ---------------- 7) visit loss + outputs ----------------
__global__ __launch_bounds__(256) void finalize_kernel(float* __restrict__ out) {
    __shared__ float red[8];
    int tid = threadIdx.x;
    float s = 0.f;
    for (int m = tid; m < N_; m += 256)
        s += logf(EPS + g_vp[m] * (1.0f / N_));
    #pragma unroll
    for (int o = 16; o; o >>= 1) s += __shfl_xor_sync(~0u, s, o);
    if ((tid & 31) == 0) red[tid >> 5] = s;
    __syncthreads();
    if (tid == 0) {
        float t = 0.f;
        for (int w = 0; w < 8; w++) t += red[w];
        out[1] = -t * (1.0f / N_);              // visit_loss
        out[0] = -g_walkerAcc * (1.0f / N_);    // walker_loss
    }
}

// ---------------- launch ----------------
extern "C" void kernel_launch(void* const* d_in, const int* in_sizes, int n_in,
                              void* d_out, int out_size) {
    const float* a = (const float*)d_in[0];
    const float* b = (const float*)d_in[1];
    const void* labels = d_in[2];
    float* out = (float*)d_out;

    init_kernel<<<16, 512>>>();
    dim3 gp(128, 128);
    gemm_p_kernel<<<gp, 256>>>(a, b);
    recip_kernel<<<16, 512>>>();
    uv_vp_kernel<<<dim3(64, 8), 256>>>();
    prep1_kernel<<<1, 256>>>(labels);
    prep2_kernel<<<32, 256>>>(labels);
    walker_kernel<<<512, 256>>>();
    finalize_kernel<<<1, 256>>>(out);
}

// round 9
// speedup vs baseline: 1.2036x; 1.2036x over previous
#include <cuda_runtime.h>
#include <cuda_bf16.h>
#include <mma.h>
#include <cstdint>

using namespace nvcuda;

#define N_ 8192
#define D_ 128
#define NLAB 10
#define SCALE 0.08838834764831845f   // 1/sqrt(128)
#define EPS 1e-8f
#define TW 128                        // walker tile width
#define KST 72                        // smem k-stride (64 data + 8 pad) in bf16

// ---------------- scratch (device globals: allocation-free) ----------------
static __device__ __nv_bfloat16 g_E16[(size_t)N_ * N_];  // exp(p) bf16 (128 MB)
static __device__ __nv_bfloat16 g_U[(size_t)N_ * N_];    // ab      (128 MB)
static __device__ __nv_bfloat16 g_V[(size_t)N_ * N_];    // ba^T    (128 MB)
static __device__ __align__(16) __nv_bfloat16 g_zero[128]; // stays 0 (never written)
static __device__ float g_rsum[N_];
static __device__ float g_csum[N_];
static __device__ float g_vp[N_];
static __device__ int   g_cnt[NLAB];
static __device__ int   g_startL[NLAB + 1];
static __device__ int   g_idx[N_];
static __device__ int   g_tilesL[NLAB];
static __device__ int   g_tileStart[NLAB + 1];
static __device__ int   g_numTiles;
static __device__ int   g_isI64;
static __device__ float g_walkerAcc;

__device__ __forceinline__ int get_label(const void* L, int i, int isI64) {
    int v = isI64 ? (int)((const long long*)L)[i] : ((const int*)L)[i];
    return min(max(v, 0), NLAB - 1);
}

__device__ __forceinline__ void cpa16(uint32_t saddr, const void* gptr) {
    asm volatile("cp.async.cg.shared.global [%0], [%1], 16;" :: "r"(saddr), "l"(gptr));
}
__device__ __forceinline__ void cpa_commit() {
    asm volatile("cp.async.commit_group;");
}
__device__ __forceinline__ void cpa_wait1() {
    asm volatile("cp.async.wait_group 1;");
}
__device__ __forceinline__ void cpa_wait0() {
    asm volatile("cp.async.wait_group 0;");
}

// ---------------- 0) zero the atomic accumulators ----------------
__global__ __launch_bounds__(512) void init_kernel() {
    int i = blockIdx.x * 512 + threadIdx.x;
    if (i < N_) { g_rsum[i] = 0.f; g_csum[i] = 0.f; g_vp[i] = 0.f; }
    if (i == 0) g_walkerAcc = 0.f;
}

// ---------------- 1) P = a b^T * scale; E=exp(P) bf16; fused row/col sums ----------------
__global__ __launch_bounds__(256) void gemm_p_kernel(const float* __restrict__ A,
                                                     const float* __restrict__ B) {
    __shared__ float As[32][65];
    __shared__ float Bs[32][65];
    __shared__ float rp[64][16];
    __shared__ float cp[64][16];
    int tid = threadIdx.x;
    int tx = tid & 15, ty = tid >> 4;
    int bi = blockIdx.y * 64, bj = blockIdx.x * 64;
    float acc[4][4] = {};
    for (int k0 = 0; k0 < D_; k0 += 32) {
        #pragma unroll
        for (int q = 0; q < 8; q++) {
            int l = tid + q * 256;
            int r = l >> 5, k = l & 31;
            As[k][r] = A[(size_t)(bi + r) * D_ + k0 + k];
            Bs[k][r] = B[(size_t)(bj + r) * D_ + k0 + k];
        }
        __syncthreads();
        #pragma unroll
        for (int k = 0; k < 32; k++) {
            float ra[4], rb[4];
            #pragma unroll
            for (int i = 0; i < 4; i++) ra[i] = As[k][ty * 4 + i];
            #pragma unroll
            for (int j = 0; j < 4; j++) rb[j] = Bs[k][tx * 4 + j];
            #pragma unroll
            for (int i = 0; i < 4; i++)
                #pragma unroll
                for (int j = 0; j < 4; j++) acc[i][j] += ra[i] * rb[j];
        }
        __syncthreads();
    }
    float colp[4] = {0.f, 0.f, 0.f, 0.f};
    #pragma unroll
    for (int i = 0; i < 4; i++) {
        float e[4], rowp = 0.f;
        #pragma unroll
        for (int j = 0; j < 4; j++) {
            e[j] = __expf(acc[i][j] * SCALE);
            rowp += e[j];
            colp[j] += e[j];
        }
        __nv_bfloat162 p0 = __floats2bfloat162_rn(e[0], e[1]);
        __nv_bfloat162 p1 = __floats2bfloat162_rn(e[2], e[3]);
        uint2 pk = make_uint2(*(unsigned*)&p0, *(unsigned*)&p1);
        *(uint2*)&g_E16[(size_t)(bi + ty * 4 + i) * N_ + bj + tx * 4] = pk;
        rp[ty * 4 + i][tx] = rowp;
    }
    #pragma unroll
    for (int j = 0; j < 4; j++) cp[tx * 4 + j][ty] = colp[j];
    __syncthreads();
    if (tid < 64) {
        float s = 0.f;
        #pragma unroll
        for (int k = 0; k < 16; k++) s += rp[tid][k];
        atomicAdd(&g_rsum[bi + tid], s);
    } else if (tid < 128) {
        int c = tid - 64;
        float s = 0.f;
        #pragma unroll
        for (int k = 0; k < 16; k++) s += cp[c][k];
        atomicAdd(&g_csum[bj + c], s);
    }
}

// ---------------- 2) invert sums in place ----------------
__global__ __launch_bounds__(512) void recip_kernel() {
    int i = blockIdx.x * 512 + threadIdx.x;
    if (i < N_) {
        g_rsum[i] = 1.f / g_rsum[i];
        g_csum[i] = 1.f / g_csum[i];
    }
}

// ---------------- 3) U, V (bf16) + visit column sums (vectorized) ----------------
__global__ __launch_bounds__(256) void uv_vp_kernel() {
    __shared__ float vps[128];
    int tid = threadIdx.x;
    int cg = tid & 15, rg = tid >> 4;
    int colBase = blockIdx.x * 128;
    int c = colBase + cg * 8;
    float cInv[8];
    #pragma unroll
    for (int k = 0; k < 8; k++) cInv[k] = g_csum[c + k];
    float vp[8] = {};
    int r0 = blockIdx.y * 1024 + rg;
    #pragma unroll 4
    for (int it = 0; it < 64; it++) {
        int r = r0 + it * 16;
        size_t off = (size_t)r * N_ + c;
        uint4 ev = *(const uint4*)&g_E16[off];
        float rInv = g_rsum[r];
        float e[8];
        {
            float2 f;
            f = __bfloat1622float2(*(__nv_bfloat162*)&ev.x); e[0] = f.x; e[1] = f.y;
            f = __bfloat1622float2(*(__nv_bfloat162*)&ev.y); e[2] = f.x; e[3] = f.y;
            f = __bfloat1622float2(*(__nv_bfloat162*)&ev.z); e[4] = f.x; e[5] = f.y;
            f = __bfloat1622float2(*(__nv_bfloat162*)&ev.w); e[6] = f.x; e[7] = f.y;
        }
        float u[8], v[8];
        #pragma unroll
        for (int k = 0; k < 8; k++) { u[k] = e[k] * rInv; v[k] = e[k] * cInv[k]; vp[k] += u[k]; }
        uint4 up, vv;
        __nv_bfloat162 t;
        t = __floats2bfloat162_rn(u[0], u[1]); up.x = *(unsigned*)&t;
        t = __floats2bfloat162_rn(u[2], u[3]); up.y = *(unsigned*)&t;
        t = __floats2bfloat162_rn(u[4], u[5]); up.z = *(unsigned*)&t;
        t = __floats2bfloat162_rn(u[6], u[7]); up.w = *(unsigned*)&t;
        t = __floats2bfloat162_rn(v[0], v[1]); vv.x = *(unsigned*)&t;
        t = __floats2bfloat162_rn(v[2], v[3]); vv.y = *(unsigned*)&t;
        t = __floats2bfloat162_rn(v[4], v[5]); vv.z = *(unsigned*)&t;
        t = __floats2bfloat162_rn(v[6], v[7]); vv.w = *(unsigned*)&t;
        *(uint4*)&g_U[off] = up;
        *(uint4*)&g_V[off] = vv;
    }
    if (tid < 128) vps[tid] = 0.f;
    __syncthreads();
    #pragma unroll
    for (int k = 0; k < 8; k++) atomicAdd(&vps[cg * 8 + k], vp[k]);
    __syncthreads();
    if (tid < 128) atomicAdd(&g_vp[colBase + tid], vps[tid]);
}

// ---------------- 4) dtype probe + label histogram + tile bookkeeping ----------------
__global__ __launch_bounds__(256) void prep1_kernel(const void* __restrict__ labels) {
    __shared__ int scnt[NLAB];
    __shared__ int oddNonzero;
    int tid = threadIdx.x;
    if (tid < NLAB) scnt[tid] = 0;
    if (tid == 0) oddNonzero = 0;
    __syncthreads();
    {
        const int* w = (const int*)labels;
        int local = 0;
        for (int i = tid; i < N_ / 2; i += 256)
            if (w[2 * i + 1] != 0) local = 1;
        if (local) oddNonzero = 1;
    }
    __syncthreads();
    int isI64 = !oddNonzero;
    if (tid == 0) g_isI64 = isI64;

    for (int i = tid; i < N_; i += 256)
        atomicAdd(&scnt[get_label(labels, i, isI64)], 1);
    __syncthreads();
    if (tid == 0) {
        int st = 0, ts = 0;
        for (int l = 0; l < NLAB; l++) {
            int cnum = scnt[l];
            g_cnt[l] = cnum;
            g_startL[l] = st; st += cnum;
            int tl = (cnum + TW - 1) / TW;
            g_tilesL[l] = tl;
            g_tileStart[l] = ts; ts += tl * tl;
        }
        g_startL[NLAB] = st;
        g_tileStart[NLAB] = ts;
        g_numTiles = ts;
    }
}

// ---------------- 5) deterministic stable scatter of indices by label ----------------
__global__ __launch_bounds__(256) void prep2_kernel(const void* __restrict__ labels) {
    __shared__ unsigned char slab[N_];
    int tid = threadIdx.x;
    int isI64 = g_isI64;
    for (int i = tid; i < N_; i += 256)
        slab[i] = (unsigned char)get_label(labels, i, isI64);
    __syncthreads();
    int i = blockIdx.x * 256 + tid;
    unsigned char lab = slab[i];
    int pos = 0;
    for (int q = 0; q < i; q++) pos += (slab[q] == lab);
    g_idx[g_startL[lab] + pos] = i;
}

// ---------------- 6) walker: 128x128 tiles, cp.async double-buffered, wmma ----------------
__global__ __launch_bounds__(256) void walker_kernel() {
    extern __shared__ __align__(16) char dsm[];
    // layout: Us[2][TW*KST], Vs[2][TW*KST]  (bf16)
    __nv_bfloat16* Us = (__nv_bfloat16*)dsm;
    __nv_bfloat16* Vs = Us + 2 * TW * KST;
    __shared__ int Ridx[TW], Cidx[TW];
    __shared__ float red[8];

    int tid = threadIdx.x;
    int warp = tid >> 5, lane = tid & 31;
    int wr = warp >> 1;        // 0..3 : 32-row band
    int wc = warp & 1;         // 0..1 : 64-col band
    int numTiles = g_numTiles;
    float blockAcc = 0.f;

    // per-thread copy coordinates: 4 chunks of 16B per matrix per stage
    int crow[4], ckk[4];
    #pragma unroll
    for (int q = 0; q < 4; q++) {
        int e = tid + q * 256;
        crow[q] = e >> 3;
        ckk[q] = (e & 7) * 8;
    }
    uint32_t usBase = (uint32_t)__cvta_generic_to_shared(Us);
    uint32_t vsBase = (uint32_t)__cvta_generic_to_shared(Vs);

    for (int t = blockIdx.x; t < numTiles; t += gridDim.x) {
        int L = 0;
        while (t >= g_tileStart[L + 1]) L++;
        int local = t - g_tileStart[L];
        int tl = g_tilesL[L];
        int nL = g_cnt[L];
        int base = g_startL[L];
        int ti = local / tl, tj = local % tl;

        if (tid < TW) {
            int r = ti * TW + tid;
            Ridx[tid] = (r < nL) ? g_idx[base + r] : -1;
            int c = tj * TW + tid;
            Cidx[tid] = (c < nL) ? g_idx[base + c] : -1;
        }
        wmma::fragment<wmma::accumulator, 16, 16, 16, float> cf[2][4];
        #pragma unroll
        for (int i = 0; i < 2; i++)
            #pragma unroll
            for (int j = 0; j < 4; j++) wmma::fill_fragment(cf[i][j], 0.f);
        __syncthreads();   // Ridx/Cidx visible

        // prologue: stage 0 <- k0 = 0
        #pragma unroll
        for (int q = 0; q < 4; q++) {
            int r = crow[q], kk = ckk[q];
            int gi = Ridx[r], gj = Cidx[r];
            const void* su = (gi >= 0) ? (const void*)&g_U[(size_t)gi * N_ + kk]
                                       : (const void*)&g_zero[kk];
            const void* sv = (gj >= 0) ? (const void*)&g_V[(size_t)gj * N_ + kk]
                                       : (const void*)&g_zero[kk];
            cpa16(usBase + (r * KST + kk) * 2, su);
            cpa16(vsBase + (r * KST + kk) * 2, sv);
        }
        cpa_commit();

        int stage = 0;
        for (int k0 = 0; k0 < N_; k0 += 64) {
            int nxt = k0 + 64;
            if (nxt < N_) {
                int soff = (stage ^ 1) * TW * KST;
                #pragma unroll
                for (int q = 0; q < 4; q++) {
                    int r = crow[q], kk = ckk[q];
                    int gi = Ridx[r], gj = Cidx[r];
                    const void* su = (gi >= 0) ? (const void*)&g_U[(size_t)gi * N_ + nxt + kk]
                                               : (const void*)&g_zero[kk];
                    const void* sv = (gj >= 0) ? (const void*)&g_V[(size_t)gj * N_ + nxt + kk]
                                               : (const void*)&g_zero[kk];
                    cpa16(usBase + (soff + r * KST + kk) * 2, su);
                    cpa16(vsBase + (soff + r * KST + kk) * 2, sv);
                }
                cpa_commit();
                cpa_wait1();
            } else {
                cpa_wait0();
            }
            __syncthreads();   // current stage complete for all threads

            const __nv_bfloat16* Uc = Us + stage * TW * KST;
            const __nv_bfloat16* Vc = Vs + stage * TW * KST;
            #pragma unroll
            for (int ks = 0; ks < 4; ks++) {
                wmma::fragment<wmma::matrix_a, 16, 16, 16, __nv_bfloat16, wmma::row_major> a0, a1;
                wmma::load_matrix_sync(a0, &Uc[(wr * 32) * KST + ks * 16], KST);
                wmma::load_matrix_sync(a1, &Uc[(wr * 32 + 16) * KST + ks * 16], KST);
                #pragma unroll
                for (int j = 0; j < 4; j++) {
                    wmma::fragment<wmma::matrix_b, 16, 16, 16, __nv_bfloat16, wmma::col_major> b;
                    wmma::load_matrix_sync(b, &Vc[(wc * 64 + j * 16) * KST + ks * 16], KST);
                    wmma::mma_sync(cf[0][j], a0, b, cf[0][j]);
                    wmma::mma_sync(cf[1][j], a1, b, cf[1][j]);
                }
            }
            __syncthreads();   // all reads of this stage done before it is refilled
            stage ^= 1;
        }

        // epilogue: per-warp fragment log-reduce; reuse stage smem as scratch
        float* wscr = (float*)dsm + warp * 256;
        int rlim = nL - ti * TW;
        int clim = nL - tj * TW;
        float s = 0.f;
        #pragma unroll
        for (int i2 = 0; i2 < 2; i2++)
            #pragma unroll
            for (int j4 = 0; j4 < 4; j4++) {
                wmma::store_matrix_sync(wscr, cf[i2][j4], 16, wmma::mem_row_major);
                __syncwarp();
                #pragma unroll
                for (int q = 0; q < 8; q++) {
                    int idx = lane + q * 32;
                    int lr = wr * 32 + i2 * 16 + (idx >> 4);
                    int lc = wc * 64 + j4 * 16 + (idx & 15);
                    if (lr < rlim && lc < clim) s += logf(EPS + wscr[idx]);
                }
                __syncwarp();
            }
        #pragma unroll
        for (int o = 16; o; o >>= 1) s += __shfl_xor_sync(~0u, s, o);
        if (lane == 0) red[warp] = s;
        __syncthreads();
        if (tid == 0) {
            float ts = 0.f;
            for (int w = 0; w < 8; w++) ts += red[w];
            blockAcc += ts / (float)nL;
        }
        __syncthreads();
    }
    if (tid == 0) atomicAdd(&g_walkerAcc, blockAcc);
}

// ---------------- 7) visit loss + outputs ----------------
__global__ __launch_bounds__(256) void finalize_kernel(float* __restrict__ out) {
    __shared__ float red[8];
    int tid = threadIdx.x;
    float s = 0.f;
    for (int m = tid; m < N_; m += 256)
        s += logf(EPS + g_vp[m] * (1.0f / N_));
    #pragma unroll
    for (int o = 16; o; o >>= 1) s += __shfl_xor_sync(~0u, s, o);
    if ((tid & 31) == 0) red[tid >> 5] = s;
    __syncthreads();
    if (tid == 0) {
        float t = 0.f;
        for (int w = 0; w < 8; w++) t += red[w];
        out[1] = -t * (1.0f / N_);              // visit_loss
        out[0] = -g_walkerAcc * (1.0f / N_);    // walker_loss
    }
}

// ---------------- launch ----------------
extern "C" void kernel_launch(void* const* d_in, const int* in_sizes, int n_in,
                              void* d_out, int out_size) {
    const float* a = (const float*)d_in[0];
    const float* b = (const float*)d_in[1];
    const void* labels = d_in[2];
    float* out = (float*)d_out;

    const int walkerSmem = 4 * TW * KST * 2;   // 73728 bytes
    static int configured = 0;
    if (!configured) {
        cudaFuncSetAttribute(walker_kernel,
                             cudaFuncAttributeMaxDynamicSharedMemorySize, walkerSmem);
        configured = 1;
    }

    init_kernel<<<16, 512>>>();
    dim3 gp(128, 128);
    gemm_p_kernel<<<gp, 256>>>(a, b);
    recip_kernel<<<16, 512>>>();
    uv_vp_kernel<<<dim3(64, 8), 256>>>();
    prep1_kernel<<<1, 256>>>(labels);
    prep2_kernel<<<32, 256>>>(labels);
    walker_kernel<<<2048, 256, walkerSmem>>>();
    finalize_kernel<<<1, 256>>>(out);
}

// round 12
// speedup vs baseline: 1.4599x; 1.2129x over previous
#include <cuda_runtime.h>
#include <cuda_bf16.h>
#include <mma.h>
#include <cstdint>

using namespace nvcuda;

#define N_ 8192
#define D_ 128
#define NLAB 10
#define SCALE 0.08838834764831845f   // 1/sqrt(128)
#define EPS 1e-8f
#define TW 128                        // walker tile width
#define KST 72                        // walker smem k-stride (64 data + 8 pad) in bf16
#define GLD 40                        // gemm smem row stride (32 data + 8 pad) in bf16

// ---------------- scratch (device globals: allocation-free) ----------------
static __device__ __nv_bfloat16 g_E16[(size_t)N_ * N_];  // exp(p) bf16 (128 MB)
static __device__ __nv_bfloat16 g_U[(size_t)N_ * N_];    // ab      (128 MB)
static __device__ __nv_bfloat16 g_V[(size_t)N_ * N_];    // ba^T    (128 MB)
static __device__ __nv_bfloat16 g_ah[(size_t)N_ * D_];   // bf16 hi/lo operands
static __device__ __nv_bfloat16 g_al[(size_t)N_ * D_];
static __device__ __nv_bfloat16 g_bh[(size_t)N_ * D_];
static __device__ __nv_bfloat16 g_bl[(size_t)N_ * D_];
static __device__ __align__(16) __nv_bfloat16 g_zero[128]; // stays 0 (never written)
static __device__ float g_rsum[N_];
static __device__ float g_csum[N_];
static __device__ float g_vp[N_];
static __device__ int   g_cnt[NLAB];
static __device__ int   g_startL[NLAB + 1];
static __device__ int   g_idx[N_];
static __device__ int   g_tilesL[NLAB];
static __device__ int   g_tileStart[NLAB + 1];
static __device__ int   g_numTiles;
static __device__ int   g_isI64;
static __device__ float g_walkerAcc;

__device__ __forceinline__ int get_label(const void* L, int i, int isI64) {
    int v = isI64 ? (int)((const long long*)L)[i] : ((const int*)L)[i];
    return min(max(v, 0), NLAB - 1);
}

__device__ __forceinline__ void cpa16(uint32_t saddr, const void* gptr) {
    asm volatile("cp.async.cg.shared.global [%0], [%1], 16;" :: "r"(saddr), "l"(gptr));
}
__device__ __forceinline__ void cpa_commit() { asm volatile("cp.async.commit_group;"); }
__device__ __forceinline__ void cpa_wait1() { asm volatile("cp.async.wait_group 1;"); }
__device__ __forceinline__ void cpa_wait0() { asm volatile("cp.async.wait_group 0;"); }

// ---------------- 0) zero the atomic accumulators ----------------
__global__ __launch_bounds__(512) void init_kernel() {
    int i = blockIdx.x * 512 + threadIdx.x;
    if (i < N_) { g_rsum[i] = 0.f; g_csum[i] = 0.f; g_vp[i] = 0.f; }
    if (i == 0) g_walkerAcc = 0.f;
}

// ---------------- 0b) fp32 -> bf16 hi/lo split of a, b ----------------
__global__ __launch_bounds__(256) void convert_kernel(const float* __restrict__ A,
                                                      const float* __restrict__ B) {
    int i = blockIdx.x * 256 + threadIdx.x;   // grid covers N_*D_
    float a = A[i];
    __nv_bfloat16 h = __float2bfloat16(a);
    g_ah[i] = h;
    g_al[i] = __float2bfloat16(a - __bfloat162float(h));
    float b = B[i];
    __nv_bfloat16 hb = __float2bfloat16(b);
    g_bh[i] = hb;
    g_bl[i] = __float2bfloat16(b - __bfloat162float(hb));
}

// ---------------- 1) P = a b^T * scale via split-bf16 wmma; E=exp(P); fused sums ----
__global__ __launch_bounds__(256, 2) void gemm_p_tc() {
    extern __shared__ char gsm[];
    __nv_bfloat16* sm = (__nv_bfloat16*)gsm;
    __shared__ float rs[128], cs[128];

    int tid = threadIdx.x;
    int warp = tid >> 5, lane = tid & 31;
    int wr = warp & 1;       // 2 row groups of 64
    int wc = warp >> 1;      // 4 col groups of 32
    int bi = blockIdx.y * 128, bj = blockIdx.x * 128;

    const int SMAT = 128 * GLD;                 // elems per matrix-part per stage
    uint32_t smBase = (uint32_t)__cvta_generic_to_shared(sm);

    if (tid < 128) { rs[tid] = 0.f; cs[tid] = 0.f; }

    wmma::fragment<wmma::accumulator, 16, 16, 16, float> cf[4][2];
    #pragma unroll
    for (int fi = 0; fi < 4; fi++)
        #pragma unroll
        for (int fj = 0; fj < 2; fj++) wmma::fill_fragment(cf[fi][fj], 0.f);

    // loader: 2048 16B-units per stage (4 mats x 128 rows x 4), 8 per thread
    auto issue = [&](int chunk, int stage) {
        int k0 = chunk * 32;
        #pragma unroll
        for (int q = 0; q < 8; q++) {
            int linear = tid + q * 256;
            int mat = linear >> 9;
            int rem = linear & 511;
            int row = rem >> 2;
            int ce = (rem & 3) * 8;
            const __nv_bfloat16* gm = (mat == 0) ? g_ah : (mat == 1) ? g_al
                                     : (mat == 2) ? g_bh : g_bl;
            int grow = ((mat < 2) ? bi : bj) + row;
            const __nv_bfloat16* src = gm + (size_t)grow * D_ + k0 + ce;
            uint32_t dst = smBase + (uint32_t)((stage * 4 + mat) * SMAT + row * GLD + ce) * 2;
            cpa16(dst, src);
        }
        cpa_commit();
    };

    issue(0, 0);
    issue(1, 1);

    for (int c = 0; c < 4; c++) {
        if (c == 3) cpa_wait0(); else cpa_wait1();
        __syncthreads();

        const __nv_bfloat16* Ah = sm + (c & 1) * 4 * SMAT;
        const __nv_bfloat16* Al = Ah + SMAT;
        const __nv_bfloat16* Bh = Ah + 2 * SMAT;
        const __nv_bfloat16* Bl = Ah + 3 * SMAT;

        #pragma unroll
        for (int ks = 0; ks < 2; ks++) {
            wmma::fragment<wmma::matrix_b, 16, 16, 16, __nv_bfloat16, wmma::col_major> bh[2], bl[2];
            #pragma unroll
            for (int j = 0; j < 2; j++) {
                wmma::load_matrix_sync(bh[j], &Bh[(wc * 32 + j * 16) * GLD + ks * 16], GLD);
                wmma::load_matrix_sync(bl[j], &Bl[(wc * 32 + j * 16) * GLD + ks * 16], GLD);
            }
            #pragma unroll
            for (int fi = 0; fi < 4; fi++) {
                wmma::fragment<wmma::matrix_a, 16, 16, 16, __nv_bfloat16, wmma::row_major> ahf, alf;
                wmma::load_matrix_sync(ahf, &Ah[(wr * 64 + fi * 16) * GLD + ks * 16], GLD);
                wmma::load_matrix_sync(alf, &Al[(wr * 64 + fi * 16) * GLD + ks * 16], GLD);
                #pragma unroll
                for (int j = 0; j < 2; j++) {
                    wmma::mma_sync(cf[fi][j], ahf, bh[j], cf[fi][j]);
                    wmma::mma_sync(cf[fi][j], ahf, bl[j], cf[fi][j]);
                    wmma::mma_sync(cf[fi][j], alf, bh[j], cf[fi][j]);
                }
            }
        }
        if (c + 2 < 4) {
            __syncthreads();            // all reads of this stage done before refill
            issue(c + 2, c & 1);
        }
    }
    __syncthreads();                    // stages dead; reuse smem as scratch

    // epilogue: exp on fragments, E store, fused row/col partial sums
    float* wscr = (float*)gsm + warp * (16 * 20);   // 1280 B per warp
    #pragma unroll
    for (int fi = 0; fi < 4; fi++) {
        #pragma unroll
        for (int fj = 0; fj < 2; fj++) {
            #pragma unroll
            for (int e = 0; e < cf[fi][fj].num_elements; e++)
                cf[fi][fj].x[e] = __expf(cf[fi][fj].x[e] * SCALE);
            wmma::store_matrix_sync(wscr, cf[fi][fj], 20, wmma::mem_row_major);
            __syncwarp();
            if (lane < 16) {
                int r = lane;
                float vals[16], rp = 0.f;
                #pragma unroll
                for (int c2 = 0; c2 < 16; c2++) { vals[c2] = wscr[r * 20 + c2]; rp += vals[c2]; }
                uint4 p0, p1;
                __nv_bfloat162 t;
                t = __floats2bfloat162_rn(vals[0], vals[1]);   p0.x = *(unsigned*)&t;
                t = __floats2bfloat162_rn(vals[2], vals[3]);   p0.y = *(unsigned*)&t;
                t = __floats2bfloat162_rn(vals[4], vals[5]);   p0.z = *(unsigned*)&t;
                t = __floats2bfloat162_rn(vals[6], vals[7]);   p0.w = *(unsigned*)&t;
                t = __floats2bfloat162_rn(vals[8], vals[9]);   p1.x = *(unsigned*)&t;
                t = __floats2bfloat162_rn(vals[10], vals[11]); p1.y = *(unsigned*)&t;
                t = __floats2bfloat162_rn(vals[12], vals[13]); p1.z = *(unsigned*)&t;
                t = __floats2bfloat162_rn(vals[14], vals[15]); p1.w = *(unsigned*)&t;
                size_t go = (size_t)(bi + wr * 64 + fi * 16 + r) * N_ + bj + wc * 32 + fj * 16;
                *(uint4*)&g_E16[go] = p0;
                *(uint4*)&g_E16[go + 8] = p1;
                atomicAdd(&rs[wr * 64 + fi * 16 + r], rp);
            } else {
                int c2 = lane - 16;
                float cpv = 0.f;
                #pragma unroll
                for (int r = 0; r < 16; r++) cpv += wscr[r * 20 + c2];
                atomicAdd(&cs[wc * 32 + fj * 16 + c2], cpv);
            }
            __syncwarp();
        }
    }
    __syncthreads();
    if (tid < 128) atomicAdd(&g_rsum[bi + tid], rs[tid]);
    else atomicAdd(&g_csum[bj + tid - 128], cs[tid - 128]);
}

// ---------------- 2) invert sums in place ----------------
__global__ __launch_bounds__(512) void recip_kernel() {
    int i = blockIdx.x * 512 + threadIdx.x;
    if (i < N_) {
        g_rsum[i] = 1.f / g_rsum[i];
        g_csum[i] = 1.f / g_csum[i];
    }
}

// ---------------- 3) U, V (bf16) + visit column sums (vectorized) ----------------
__global__ __launch_bounds__(256) void uv_vp_kernel() {
    __shared__ float vps[128];
    int tid = threadIdx.x;
    int cg = tid & 15, rg = tid >> 4;
    int colBase = blockIdx.x * 128;
    int c = colBase + cg * 8;
    float cInv[8];
    #pragma unroll
    for (int k = 0; k < 8; k++) cInv[k] = g_csum[c + k];
    float vp[8] = {};
    int r0 = blockIdx.y * 1024 + rg;
    #pragma unroll 4
    for (int it = 0; it < 64; it++) {
        int r = r0 + it * 16;
        size_t off = (size_t)r * N_ + c;
        uint4 ev = *(const uint4*)&g_E16[off];
        float rInv = g_rsum[r];
        float e[8];
        {
            float2 f;
            f = __bfloat1622float2(*(__nv_bfloat162*)&ev.x); e[0] = f.x; e[1] = f.y;
            f = __bfloat1622float2(*(__nv_bfloat162*)&ev.y); e[2] = f.x; e[3] = f.y;
            f = __bfloat1622float2(*(__nv_bfloat162*)&ev.z); e[4] = f.x; e[5] = f.y;
            f = __bfloat1622float2(*(__nv_bfloat162*)&ev.w); e[6] = f.x; e[7] = f.y;
        }
        float u[8], v[8];
        #pragma unroll
        for (int k = 0; k < 8; k++) { u[k] = e[k] * rInv; v[k] = e[k] * cInv[k]; vp[k] += u[k]; }
        uint4 up, vv;
        __nv_bfloat162 t;
        t = __floats2bfloat162_rn(u[0], u[1]); up.x = *(unsigned*)&t;
        t = __floats2bfloat162_rn(u[2], u[3]); up.y = *(unsigned*)&t;
        t = __floats2bfloat162_rn(u[4], u[5]); up.z = *(unsigned*)&t;
        t = __floats2bfloat162_rn(u[6], u[7]); up.w = *(unsigned*)&t;
        t = __floats2bfloat162_rn(v[0], v[1]); vv.x = *(unsigned*)&t;
        t = __floats2bfloat162_rn(v[2], v[3]); vv.y = *(unsigned*)&t;
        t = __floats2bfloat162_rn(v[4], v[5]); vv.z = *(unsigned*)&t;
        t = __floats2bfloat162_rn(v[6], v[7]); vv.w = *(unsigned*)&t;
        *(uint4*)&g_U[off] = up;
        *(uint4*)&g_V[off] = vv;
    }
    if (tid < 128) vps[tid] = 0.f;
    __syncthreads();
    #pragma unroll
    for (int k = 0; k < 8; k++) atomicAdd(&vps[cg * 8 + k], vp[k]);
    __syncthreads();
    if (tid < 128) atomicAdd(&g_vp[colBase + tid], vps[tid]);
}

// ---------------- 4) dtype probe + label histogram + tile bookkeeping ----------------
__global__ __launch_bounds__(256) void prep1_kernel(const void* __restrict__ labels) {
    __shared__ int scnt[NLAB];
    __shared__ int oddNonzero;
    int tid = threadIdx.x;
    if (tid < NLAB) scnt[tid] = 0;
    if (tid == 0) oddNonzero = 0;
    __syncthreads();
    {
        const int* w = (const int*)labels;
        int local = 0;
        for (int i = tid; i < N_ / 2; i += 256)
            if (w[2 * i + 1] != 0) local = 1;
        if (local) oddNonzero = 1;
    }
    __syncthreads();
    int isI64 = !oddNonzero;
    if (tid == 0) g_isI64 = isI64;

    for (int i = tid; i < N_; i += 256)
        atomicAdd(&scnt[get_label(labels, i, isI64)], 1);
    __syncthreads();
    if (tid == 0) {
        int st = 0, ts = 0;
        for (int l = 0; l < NLAB; l++) {
            int cnum = scnt[l];
            g_cnt[l] = cnum;
            g_startL[l] = st; st += cnum;
            int tl = (cnum + TW - 1) / TW;
            g_tilesL[l] = tl;
            g_tileStart[l] = ts; ts += tl * tl;
        }
        g_startL[NLAB] = st;
        g_tileStart[NLAB] = ts;
        g_numTiles = ts;
    }
}

// ---------------- 5) deterministic stable scatter of indices by label ----------------
__global__ __launch_bounds__(256) void prep2_kernel(const void* __restrict__ labels) {
    __shared__ unsigned char slab[N_];
    int tid = threadIdx.x;
    int isI64 = g_isI64;
    for (int i = tid; i < N_; i += 256)
        slab[i] = (unsigned char)get_label(labels, i, isI64);
    __syncthreads();
    int i = blockIdx.x * 256 + tid;
    unsigned char lab = slab[i];
    int pos = 0;
    for (int q = 0; q < i; q++) pos += (slab[q] == lab);
    g_idx[g_startL[lab] + pos] = i;
}

// ---------------- 6) walker: 128x128 tiles, cp.async double-buffered, wmma ----------------
__global__ __launch_bounds__(256) void walker_kernel() {
    extern __shared__ __align__(16) char dsm[];
    __nv_bfloat16* Us = (__nv_bfloat16*)dsm;
    __nv_bfloat16* Vs = Us + 2 * TW * KST;
    __shared__ int Ridx[TW], Cidx[TW];
    __shared__ float red[8];

    int tid = threadIdx.x;
    int warp = tid >> 5, lane = tid & 31;
    int wr = warp >> 1;
    int wc = warp & 1;
    int numTiles = g_numTiles;
    float blockAcc = 0.f;

    int crow[4], ckk[4];
    #pragma unroll
    for (int q = 0; q < 4; q++) {
        int e = tid + q * 256;
        crow[q] = e >> 3;
        ckk[q] = (e & 7) * 8;
    }
    uint32_t usBase = (uint32_t)__cvta_generic_to_shared(Us);
    uint32_t vsBase = (uint32_t)__cvta_generic_to_shared(Vs);

    for (int t = blockIdx.x; t < numTiles; t += gridDim.x) {
        int L = 0;
        while (t >= g_tileStart[L + 1]) L++;
        int local = t - g_tileStart[L];
        int tl = g_tilesL[L];
        int nL = g_cnt[L];
        int base = g_startL[L];
        int ti = local / tl, tj = local % tl;

        if (tid < TW) {
            int r = ti * TW + tid;
            Ridx[tid] = (r < nL) ? g_idx[base + r] : -1;
            int c = tj * TW + tid;
            Cidx[tid] = (c < nL) ? g_idx[base + c] : -1;
        }
        wmma::fragment<wmma::accumulator, 16, 16, 16, float> cf[2][4];
        #pragma unroll
        for (int i = 0; i < 2; i++)
            #pragma unroll
            for (int j = 0; j < 4; j++) wmma::fill_fragment(cf[i][j], 0.f);
        __syncthreads();

        #pragma unroll
        for (int q = 0; q < 4; q++) {
            int r = crow[q], kk = ckk[q];
            int gi = Ridx[r], gj = Cidx[r];
            const void* su = (gi >= 0) ? (const void*)&g_U[(size_t)gi * N_ + kk]
                                       : (const void*)&g_zero[kk];
            const void* sv = (gj >= 0) ? (const void*)&g_V[(size_t)gj * N_ + kk]
                                       : (const void*)&g_zero[kk];
            cpa16(usBase + (r * KST + kk) * 2, su);
            cpa16(vsBase + (r * KST + kk) * 2, sv);
        }
        cpa_commit();

        int stage = 0;
        for (int k0 = 0; k0 < N_; k0 += 64) {
            int nxt = k0 + 64;
            if (nxt < N_) {
                int soff = (stage ^ 1) * TW * KST;
                #pragma unroll
                for (int q = 0; q < 4; q++) {
                    int r = crow[q], kk = ckk[q];
                    int gi = Ridx[r], gj = Cidx[r];
                    const void* su = (gi >= 0) ? (const void*)&g_U[(size_t)gi * N_ + nxt + kk]
                                               : (const void*)&g_zero[kk];
                    const void* sv = (gj >= 0) ? (const void*)&g_V[(size_t)gj * N_ + nxt + kk]
                                               : (const void*)&g_zero[kk];
                    cpa16(usBase + (soff + r * KST + kk) * 2, su);
                    cpa16(vsBase + (soff + r * KST + kk) * 2, sv);
                }
                cpa_commit();
                cpa_wait1();
            } else {
                cpa_wait0();
            }
            __syncthreads();

            const __nv_bfloat16* Uc = Us + stage * TW * KST;
            const __nv_bfloat16* Vc = Vs + stage * TW * KST;
            #pragma unroll
            for (int ks = 0; ks < 4; ks++) {
                wmma::fragment<wmma::matrix_a, 16, 16, 16, __nv_bfloat16, wmma::row_major> a0, a1;
                wmma::load_matrix_sync(a0, &Uc[(wr * 32) * KST + ks * 16], KST);
                wmma::load_matrix_sync(a1, &Uc[(wr * 32 + 16) * KST + ks * 16], KST);
                #pragma unroll
                for (int j = 0; j < 4; j++) {
                    wmma::fragment<wmma::matrix_b, 16, 16, 16, __nv_bfloat16, wmma::col_major> b;
                    wmma::load_matrix_sync(b, &Vc[(wc * 64 + j * 16) * KST + ks * 16], KST);
                    wmma::mma_sync(cf[0][j], a0, b, cf[0][j]);
                    wmma::mma_sync(cf[1][j], a1, b, cf[1][j]);
                }
            }
            __syncthreads();
            stage ^= 1;
        }

        float* wscr = (float*)dsm + warp * 256;
        int rlim = nL - ti * TW;
        int clim = nL - tj * TW;
        float s = 0.f;
        #pragma unroll
        for (int i2 = 0; i2 < 2; i2++)
            #pragma unroll
            for (int j4 = 0; j4 < 4; j4++) {
                wmma::store_matrix_sync(wscr, cf[i2][j4], 16, wmma::mem_row_major);
                __syncwarp();
                #pragma unroll
                for (int q = 0; q < 8; q++) {
                    int idx = lane + q * 32;
                    int lr = wr * 32 + i2 * 16 + (idx >> 4);
                    int lc = wc * 64 + j4 * 16 + (idx & 15);
                    if (lr < rlim && lc < clim) s += logf(EPS + wscr[idx]);
                }
                __syncwarp();
            }
        #pragma unroll
        for (int o = 16; o; o >>= 1) s += __shfl_xor_sync(~0u, s, o);
        if (lane == 0) red[warp] = s;
        __syncthreads();
        if (tid == 0) {
            float ts = 0.f;
            for (int w = 0; w < 8; w++) ts += red[w];
            blockAcc += ts / (float)nL;
        }
        __syncthreads();
    }
    if (tid == 0) atomicAdd(&g_walkerAcc, blockAcc);
}

// ---------------- 7) visit loss + outputs ----------------
__global__ __launch_bounds__(256) void finalize_kernel(float* __restrict__ out) {
    __shared__ float red[8];
    int tid = threadIdx.x;
    float s = 0.f;
    for (int m = tid; m < N_; m += 256)
        s += logf(EPS + g_vp[m] * (1.0f / N_));
    #pragma unroll
    for (int o = 16; o; o >>= 1) s += __shfl_xor_sync(~0u, s, o);
    if ((tid & 31) == 0) red[tid >> 5] = s;
    __syncthreads();
    if (tid == 0) {
        float t = 0.f;
        for (int w = 0; w < 8; w++) t += red[w];
        out[1] = -t * (1.0f / N_);              // visit_loss
        out[0] = -g_walkerAcc * (1.0f / N_);    // walker_loss
    }
}

// ---------------- launch ----------------
extern "C" void kernel_launch(void* const* d_in, const int* in_sizes, int n_in,
                              void* d_out, int out_size) {
    const float* a = (const float*)d_in[0];
    const float* b = (const float*)d_in[1];
    const void* labels = d_in[2];
    float* out = (float*)d_out;

    const int walkerSmem = 4 * TW * KST * 2;     // 73728 bytes
    const int gemmSmem = 2 * 4 * 128 * GLD * 2;  // 81920 bytes
    static int configured = 0;
    if (!configured) {
        cudaFuncSetAttribute(walker_kernel,
                             cudaFuncAttributeMaxDynamicSharedMemorySize, walkerSmem);
        cudaFuncSetAttribute(gemm_p_tc,
                             cudaFuncAttributeMaxDynamicSharedMemorySize, gemmSmem);
        configured = 1;
    }

    init_kernel<<<16, 512>>>();
    convert_kernel<<<(N_ * D_) / 256, 256>>>(a, b);
    gemm_p_tc<<<dim3(64, 64), 256, gemmSmem>>>();
    recip_kernel<<<16, 512>>>();
    uv_vp_kernel<<<dim3(64, 8), 256>>>();
    prep1_kernel<<<1, 256>>>(labels);
    prep2_kernel<<<32, 256>>>(labels);
    walker_kernel<<<2048, 256, walkerSmem>>>();
    finalize_kernel<<<1, 256>>>(out);
}

// round 13
// speedup vs baseline: 2.1644x; 1.4826x over previous
#include <cuda_runtime.h>
#include <cuda_bf16.h>
#include <mma.h>
#include <cstdint>

using namespace nvcuda;

#define N_ 8192
#define D_ 128
#define NLAB 10
#define SCALE 0.08838834764831845f   // 1/sqrt(128)
#define EPS 1e-8f
#define TW 128                        // walker tile width
#define KST 72                        // walker smem k-stride (64 data + 8 pad) in bf16
#define GLD 40                        // gemm smem row stride (32 data + 8 pad) in bf16

// ---------------- scratch (device globals: allocation-free) ----------------
static __device__ __nv_bfloat16 g_E16[(size_t)N_ * N_];  // exp(p) bf16 (128 MB)
static __device__ __nv_bfloat16 g_W[(size_t)N_ * N_];    // E * sqrt(csumInv)  (128 MB)
static __device__ __nv_bfloat16 g_ah[(size_t)N_ * D_];   // bf16 hi/lo operands
static __device__ __nv_bfloat16 g_al[(size_t)N_ * D_];
static __device__ __nv_bfloat16 g_bh[(size_t)N_ * D_];
static __device__ __nv_bfloat16 g_bl[(size_t)N_ * D_];
static __device__ __align__(16) __nv_bfloat16 g_zero[128]; // stays 0 (never written)
static __device__ float g_rsum[N_];   // row sums -> rInv after recip
static __device__ float g_csum[N_];   // col sums -> cInv after recip
static __device__ float g_vp[N_];
static __device__ int   g_cnt[NLAB];
static __device__ int   g_startL[NLAB + 1];
static __device__ int   g_idx[N_];
static __device__ int   g_tilesL[NLAB];
static __device__ int   g_tileStart[NLAB + 1];
static __device__ int   g_numTiles;
static __device__ int   g_isI64;
static __device__ float g_walkerAcc;

__device__ __forceinline__ int get_label(const void* L, int i, int isI64) {
    int v = isI64 ? (int)((const long long*)L)[i] : ((const int*)L)[i];
    return min(max(v, 0), NLAB - 1);
}

__device__ __forceinline__ void cpa16(uint32_t saddr, const void* gptr) {
    asm volatile("cp.async.cg.shared.global [%0], [%1], 16;" :: "r"(saddr), "l"(gptr));
}
__device__ __forceinline__ void cpa_commit() { asm volatile("cp.async.commit_group;"); }
__device__ __forceinline__ void cpa_wait1() { asm volatile("cp.async.wait_group 1;"); }
__device__ __forceinline__ void cpa_wait0() { asm volatile("cp.async.wait_group 0;"); }

// ---------------- 0) zero the atomic accumulators ----------------
__global__ __launch_bounds__(512) void init_kernel() {
    int i = blockIdx.x * 512 + threadIdx.x;
    if (i < N_) { g_rsum[i] = 0.f; g_csum[i] = 0.f; g_vp[i] = 0.f; }
    if (i == 0) g_walkerAcc = 0.f;
}

// ---------------- 0b) fp32 -> bf16 hi/lo split of a, b ----------------
__global__ __launch_bounds__(256) void convert_kernel(const float* __restrict__ A,
                                                      const float* __restrict__ B) {
    int i = blockIdx.x * 256 + threadIdx.x;   // grid covers N_*D_
    float a = A[i];
    __nv_bfloat16 h = __float2bfloat16(a);
    g_ah[i] = h;
    g_al[i] = __float2bfloat16(a - __bfloat162float(h));
    float b = B[i];
    __nv_bfloat16 hb = __float2bfloat16(b);
    g_bh[i] = hb;
    g_bl[i] = __float2bfloat16(b - __bfloat162float(hb));
}

// ---------------- 1) P = a b^T * scale via split-bf16 wmma; E=exp(P); fused sums ----
__global__ __launch_bounds__(256, 2) void gemm_p_tc() {
    extern __shared__ char gsm[];
    __nv_bfloat16* sm = (__nv_bfloat16*)gsm;
    __shared__ float rs[128], cs[128];

    int tid = threadIdx.x;
    int warp = tid >> 5, lane = tid & 31;
    int wr = warp & 1;       // 2 row groups of 64
    int wc = warp >> 1;      // 4 col groups of 32
    int bi = blockIdx.y * 128, bj = blockIdx.x * 128;

    const int SMAT = 128 * GLD;
    uint32_t smBase = (uint32_t)__cvta_generic_to_shared(sm);

    if (tid < 128) { rs[tid] = 0.f; cs[tid] = 0.f; }

    wmma::fragment<wmma::accumulator, 16, 16, 16, float> cf[4][2];
    #pragma unroll
    for (int fi = 0; fi < 4; fi++)
        #pragma unroll
        for (int fj = 0; fj < 2; fj++) wmma::fill_fragment(cf[fi][fj], 0.f);

    auto issue = [&](int chunk, int stage) {
        int k0 = chunk * 32;
        #pragma unroll
        for (int q = 0; q < 8; q++) {
            int linear = tid + q * 256;
            int mat = linear >> 9;
            int rem = linear & 511;
            int row = rem >> 2;
            int ce = (rem & 3) * 8;
            const __nv_bfloat16* gm = (mat == 0) ? g_ah : (mat == 1) ? g_al
                                     : (mat == 2) ? g_bh : g_bl;
            int grow = ((mat < 2) ? bi : bj) + row;
            const __nv_bfloat16* src = gm + (size_t)grow * D_ + k0 + ce;
            uint32_t dst = smBase + (uint32_t)((stage * 4 + mat) * SMAT + row * GLD + ce) * 2;
            cpa16(dst, src);
        }
        cpa_commit();
    };

    issue(0, 0);
    issue(1, 1);

    for (int c = 0; c < 4; c++) {
        if (c == 3) cpa_wait0(); else cpa_wait1();
        __syncthreads();

        const __nv_bfloat16* Ah = sm + (c & 1) * 4 * SMAT;
        const __nv_bfloat16* Al = Ah + SMAT;
        const __nv_bfloat16* Bh = Ah + 2 * SMAT;
        const __nv_bfloat16* Bl = Ah + 3 * SMAT;

        #pragma unroll
        for (int ks = 0; ks < 2; ks++) {
            wmma::fragment<wmma::matrix_b, 16, 16, 16, __nv_bfloat16, wmma::col_major> bh[2], bl[2];
            #pragma unroll
            for (int j = 0; j < 2; j++) {
                wmma::load_matrix_sync(bh[j], &Bh[(wc * 32 + j * 16) * GLD + ks * 16], GLD);
                wmma::load_matrix_sync(bl[j], &Bl[(wc * 32 + j * 16) * GLD + ks * 16], GLD);
            }
            #pragma unroll
            for (int fi = 0; fi < 4; fi++) {
                wmma::fragment<wmma::matrix_a, 16, 16, 16, __nv_bfloat16, wmma::row_major> ahf, alf;
                wmma::load_matrix_sync(ahf, &Ah[(wr * 64 + fi * 16) * GLD + ks * 16], GLD);
                wmma::load_matrix_sync(alf, &Al[(wr * 64 + fi * 16) * GLD + ks * 16], GLD);
                #pragma unroll
                for (int j = 0; j < 2; j++) {
                    wmma::mma_sync(cf[fi][j], ahf, bh[j], cf[fi][j]);
                    wmma::mma_sync(cf[fi][j], ahf, bl[j], cf[fi][j]);
                    wmma::mma_sync(cf[fi][j], alf, bh[j], cf[fi][j]);
                }
            }
        }
        if (c + 2 < 4) {
            __syncthreads();
            issue(c + 2, c & 1);
        }
    }
    __syncthreads();

    float* wscr = (float*)gsm + warp * (16 * 20);
    #pragma unroll
    for (int fi = 0; fi < 4; fi++) {
        #pragma unroll
        for (int fj = 0; fj < 2; fj++) {
            #pragma unroll
            for (int e = 0; e < cf[fi][fj].num_elements; e++)
                cf[fi][fj].x[e] = __expf(cf[fi][fj].x[e] * SCALE);
            wmma::store_matrix_sync(wscr, cf[fi][fj], 20, wmma::mem_row_major);
            __syncwarp();
            if (lane < 16) {
                int r = lane;
                float vals[16], rp = 0.f;
                #pragma unroll
                for (int c2 = 0; c2 < 16; c2++) { vals[c2] = wscr[r * 20 + c2]; rp += vals[c2]; }
                uint4 p0, p1;
                __nv_bfloat162 t;
                t = __floats2bfloat162_rn(vals[0], vals[1]);   p0.x = *(unsigned*)&t;
                t = __floats2bfloat162_rn(vals[2], vals[3]);   p0.y = *(unsigned*)&t;
                t = __floats2bfloat162_rn(vals[4], vals[5]);   p0.z = *(unsigned*)&t;
                t = __floats2bfloat162_rn(vals[6], vals[7]);   p0.w = *(unsigned*)&t;
                t = __floats2bfloat162_rn(vals[8], vals[9]);   p1.x = *(unsigned*)&t;
                t = __floats2bfloat162_rn(vals[10], vals[11]); p1.y = *(unsigned*)&t;
                t = __floats2bfloat162_rn(vals[12], vals[13]); p1.z = *(unsigned*)&t;
                t = __floats2bfloat162_rn(vals[14], vals[15]); p1.w = *(unsigned*)&t;
                size_t go = (size_t)(bi + wr * 64 + fi * 16 + r) * N_ + bj + wc * 32 + fj * 16;
                *(uint4*)&g_E16[go] = p0;
                *(uint4*)&g_E16[go + 8] = p1;
                atomicAdd(&rs[wr * 64 + fi * 16 + r], rp);
            } else {
                int c2 = lane - 16;
                float cpv = 0.f;
                #pragma unroll
                for (int r = 0; r < 16; r++) cpv += wscr[r * 20 + c2];
                atomicAdd(&cs[wc * 32 + fj * 16 + c2], cpv);
            }
            __syncwarp();
        }
    }
    __syncthreads();
    if (tid < 128) atomicAdd(&g_rsum[bi + tid], rs[tid]);
    else atomicAdd(&g_csum[bj + tid - 128], cs[tid - 128]);
}

// ---------------- 2) invert sums in place ----------------
__global__ __launch_bounds__(512) void recip_kernel() {
    int i = blockIdx.x * 512 + threadIdx.x;
    if (i < N_) {
        g_rsum[i] = 1.f / g_rsum[i];
        g_csum[i] = 1.f / g_csum[i];
    }
}

// ---------------- 3) W = E * sqrt(cInv) (bf16) + visit column sums ----------------
__global__ __launch_bounds__(256) void w_vp_kernel() {
    __shared__ float vps[128];
    int tid = threadIdx.x;
    int cg = tid & 15, rg = tid >> 4;
    int colBase = blockIdx.x * 128;
    int c = colBase + cg * 8;
    float sCI[8];
    #pragma unroll
    for (int k = 0; k < 8; k++) sCI[k] = sqrtf(g_csum[c + k]);
    float vp[8] = {};
    int r0 = blockIdx.y * 1024 + rg;
    #pragma unroll 4
    for (int it = 0; it < 64; it++) {
        int r = r0 + it * 16;
        size_t off = (size_t)r * N_ + c;
        uint4 ev = *(const uint4*)&g_E16[off];
        float rInv = g_rsum[r];
        float e[8];
        {
            float2 f;
            f = __bfloat1622float2(*(__nv_bfloat162*)&ev.x); e[0] = f.x; e[1] = f.y;
            f = __bfloat1622float2(*(__nv_bfloat162*)&ev.y); e[2] = f.x; e[3] = f.y;
            f = __bfloat1622float2(*(__nv_bfloat162*)&ev.z); e[4] = f.x; e[5] = f.y;
            f = __bfloat1622float2(*(__nv_bfloat162*)&ev.w); e[6] = f.x; e[7] = f.y;
        }
        float w[8];
        #pragma unroll
        for (int k = 0; k < 8; k++) { w[k] = e[k] * sCI[k]; vp[k] += e[k] * rInv; }
        uint4 wp;
        __nv_bfloat162 t;
        t = __floats2bfloat162_rn(w[0], w[1]); wp.x = *(unsigned*)&t;
        t = __floats2bfloat162_rn(w[2], w[3]); wp.y = *(unsigned*)&t;
        t = __floats2bfloat162_rn(w[4], w[5]); wp.z = *(unsigned*)&t;
        t = __floats2bfloat162_rn(w[6], w[7]); wp.w = *(unsigned*)&t;
        *(uint4*)&g_W[off] = wp;
    }
    if (tid < 128) vps[tid] = 0.f;
    __syncthreads();
    #pragma unroll
    for (int k = 0; k < 8; k++) atomicAdd(&vps[cg * 8 + k], vp[k]);
    __syncthreads();
    if (tid < 128) atomicAdd(&g_vp[colBase + tid], vps[tid]);
}

// ---------------- 4) dtype probe + label histogram + triangular tile bookkeeping ----
__global__ __launch_bounds__(256) void prep1_kernel(const void* __restrict__ labels) {
    __shared__ int scnt[NLAB];
    __shared__ int oddNonzero;
    int tid = threadIdx.x;
    if (tid < NLAB) scnt[tid] = 0;
    if (tid == 0) oddNonzero = 0;
    __syncthreads();
    {
        const int* w = (const int*)labels;
        int local = 0;
        for (int i = tid; i < N_ / 2; i += 256)
            if (w[2 * i + 1] != 0) local = 1;
        if (local) oddNonzero = 1;
    }
    __syncthreads();
    int isI64 = !oddNonzero;
    if (tid == 0) g_isI64 = isI64;

    for (int i = tid; i < N_; i += 256)
        atomicAdd(&scnt[get_label(labels, i, isI64)], 1);
    __syncthreads();
    if (tid == 0) {
        int st = 0, ts = 0;
        for (int l = 0; l < NLAB; l++) {
            int cnum = scnt[l];
            g_cnt[l] = cnum;
            g_startL[l] = st; st += cnum;
            int tl = (cnum + TW - 1) / TW;
            g_tilesL[l] = tl;
            g_tileStart[l] = ts; ts += tl * (tl + 1) / 2;   // upper triangle only
        }
        g_startL[NLAB] = st;
        g_tileStart[NLAB] = ts;
        g_numTiles = ts;
    }
}

// ---------------- 5) deterministic stable scatter of indices by label ----------------
__global__ __launch_bounds__(256) void prep2_kernel(const void* __restrict__ labels) {
    __shared__ unsigned char slab[N_];
    int tid = threadIdx.x;
    int isI64 = g_isI64;
    for (int i = tid; i < N_; i += 256)
        slab[i] = (unsigned char)get_label(labels, i, isI64);
    __syncthreads();
    int i = blockIdx.x * 256 + tid;
    unsigned char lab = slab[i];
    int pos = 0;
    for (int q = 0; q < i; q++) pos += (slab[q] == lab);
    g_idx[g_startL[lab] + pos] = i;
}

// ---------------- 6) walker: symmetric S = W W^T, upper-tri tiles, wmma ----------------
__global__ __launch_bounds__(256) void walker_kernel() {
    extern __shared__ __align__(16) char dsm[];
    __nv_bfloat16* Us = (__nv_bfloat16*)dsm;            // W rows (ti block), 2 stages
    __nv_bfloat16* Vs = Us + 2 * TW * KST;              // W rows (tj block), 2 stages
    __shared__ int Ridx[TW], Cidx[TW];
    __shared__ float rIr[TW], rIc[TW];
    __shared__ float red[8];

    int tid = threadIdx.x;
    int warp = tid >> 5, lane = tid & 31;
    int wr = warp >> 1;
    int wc = warp & 1;
    int numTiles = g_numTiles;
    float blockAcc = 0.f;

    int crow[4], ckk[4];
    #pragma unroll
    for (int q = 0; q < 4; q++) {
        int e = tid + q * 256;
        crow[q] = e >> 3;
        ckk[q] = (e & 7) * 8;
    }
    uint32_t usBase = (uint32_t)__cvta_generic_to_shared(Us);
    uint32_t vsBase = (uint32_t)__cvta_generic_to_shared(Vs);

    for (int t = blockIdx.x; t < numTiles; t += gridDim.x) {
        int L = 0;
        while (t >= g_tileStart[L + 1]) L++;
        int local = t - g_tileStart[L];
        int tl = g_tilesL[L];
        int nL = g_cnt[L];
        int base = g_startL[L];
        // triangular decode: row ti has (tl - ti) tiles (tj = ti..tl-1)
        int ti = 0, rem = local;
        while (rem >= tl - ti) { rem -= tl - ti; ti++; }
        int tj = ti + rem;
        int offdiag = (ti != tj);

        if (tid < TW) {
            int r = ti * TW + tid;
            int gi = (r < nL) ? g_idx[base + r] : -1;
            Ridx[tid] = gi;
            rIr[tid] = (gi >= 0) ? g_rsum[gi] : 0.f;
            int c = tj * TW + tid;
            int gj = (c < nL) ? g_idx[base + c] : -1;
            Cidx[tid] = gj;
            rIc[tid] = (gj >= 0) ? g_rsum[gj] : 0.f;
        }
        wmma::fragment<wmma::accumulator, 16, 16, 16, float> cf[2][4];
        #pragma unroll
        for (int i = 0; i < 2; i++)
            #pragma unroll
            for (int j = 0; j < 4; j++) wmma::fill_fragment(cf[i][j], 0.f);
        __syncthreads();

        #pragma unroll
        for (int q = 0; q < 4; q++) {
            int r = crow[q], kk = ckk[q];
            int gi = Ridx[r], gj = Cidx[r];
            const void* su = (gi >= 0) ? (const void*)&g_W[(size_t)gi * N_ + kk]
                                       : (const void*)&g_zero[kk];
            const void* sv = (gj >= 0) ? (const void*)&g_W[(size_t)gj * N_ + kk]
                                       : (const void*)&g_zero[kk];
            cpa16(usBase + (r * KST + kk) * 2, su);
            cpa16(vsBase + (r * KST + kk) * 2, sv);
        }
        cpa_commit();

        int stage = 0;
        for (int k0 = 0; k0 < N_; k0 += 64) {
            int nxt = k0 + 64;
            if (nxt < N_) {
                int soff = (stage ^ 1) * TW * KST;
                #pragma unroll
                for (int q = 0; q < 4; q++) {
                    int r = crow[q], kk = ckk[q];
                    int gi = Ridx[r], gj = Cidx[r];
                    const void* su = (gi >= 0) ? (const void*)&g_W[(size_t)gi * N_ + nxt + kk]
                                               : (const void*)&g_zero[kk];
                    const void* sv = (gj >= 0) ? (const void*)&g_W[(size_t)gj * N_ + nxt + kk]
                                               : (const void*)&g_zero[kk];
                    cpa16(usBase + (soff + r * KST + kk) * 2, su);
                    cpa16(vsBase + (soff + r * KST + kk) * 2, sv);
                }
                cpa_commit();
                cpa_wait1();
            } else {
                cpa_wait0();
            }
            __syncthreads();

            const __nv_bfloat16* Uc = Us + stage * TW * KST;
            const __nv_bfloat16* Vc = Vs + stage * TW * KST;
            #pragma unroll
            for (int ks = 0; ks < 4; ks++) {
                wmma::fragment<wmma::matrix_a, 16, 16, 16, __nv_bfloat16, wmma::row_major> a0, a1;
                wmma::load_matrix_sync(a0, &Uc[(wr * 32) * KST + ks * 16], KST);
                wmma::load_matrix_sync(a1, &Uc[(wr * 32 + 16) * KST + ks * 16], KST);
                #pragma unroll
                for (int j = 0; j < 4; j++) {
                    wmma::fragment<wmma::matrix_b, 16, 16, 16, __nv_bfloat16, wmma::col_major> b;
                    wmma::load_matrix_sync(b, &Vc[(wc * 64 + j * 16) * KST + ks * 16], KST);
                    wmma::mma_sync(cf[0][j], a0, b, cf[0][j]);
                    wmma::mma_sync(cf[1][j], a1, b, cf[1][j]);
                }
            }
            __syncthreads();
            stage ^= 1;
        }

        // epilogue: S tile -> both orientations' log contributions
        float* wscr = (float*)dsm + warp * 256;
        int rlim = nL - ti * TW;
        int clim = nL - tj * TW;
        float s = 0.f;
        #pragma unroll
        for (int i2 = 0; i2 < 2; i2++)
            #pragma unroll
            for (int j4 = 0; j4 < 4; j4++) {
                wmma::store_matrix_sync(wscr, cf[i2][j4], 16, wmma::mem_row_major);
                __syncwarp();
                #pragma unroll
                for (int q = 0; q < 8; q++) {
                    int idx = lane + q * 32;
                    int lr = wr * 32 + i2 * 16 + (idx >> 4);
                    int lc = wc * 64 + j4 * 16 + (idx & 15);
                    if (lr < rlim && lc < clim) {
                        float sv = wscr[idx];
                        s += __logf(EPS + rIr[lr] * sv);             // pair (i, j)
                        if (offdiag) s += __logf(EPS + rIc[lc] * sv); // pair (j, i)
                    }
                }
                __syncwarp();
            }
        #pragma unroll
        for (int o = 16; o; o >>= 1) s += __shfl_xor_sync(~0u, s, o);
        if (lane == 0) red[warp] = s;
        __syncthreads();
        if (tid == 0) {
            float ts = 0.f;
            for (int w = 0; w < 8; w++) ts += red[w];
            blockAcc += ts / (float)nL;
        }
        __syncthreads();
    }
    if (tid == 0) atomicAdd(&g_walkerAcc, blockAcc);
}

// ---------------- 7) visit loss + outputs ----------------
__global__ __launch_bounds__(256) void finalize_kernel(float* __restrict__ out) {
    __shared__ float red[8];
    int tid = threadIdx.x;
    float s = 0.f;
    for (int m = tid; m < N_; m += 256)
        s += logf(EPS + g_vp[m] * (1.0f / N_));
    #pragma unroll
    for (int o = 16; o; o >>= 1) s += __shfl_xor_sync(~0u, s, o);
    if ((tid & 31) == 0) red[tid >> 5] = s;
    __syncthreads();
    if (tid == 0) {
        float t = 0.f;
        for (int w = 0; w < 8; w++) t += red[w];
        out[1] = -t * (1.0f / N_);              // visit_loss
        out[0] = -g_walkerAcc * (1.0f / N_);    // walker_loss
    }
}

// ---------------- launch ----------------
extern "C" void kernel_launch(void* const* d_in, const int* in_sizes, int n_in,
                              void* d_out, int out_size) {
    const float* a = (const float*)d_in[0];
    const float* b = (const float*)d_in[1];
    const void* labels = d_in[2];
    float* out = (float*)d_out;

    const int walkerSmem = 4 * TW * KST * 2;     // 73728 bytes
    const int gemmSmem = 2 * 4 * 128 * GLD * 2;  // 81920 bytes
    static int configured = 0;
    if (!configured) {
        cudaFuncSetAttribute(walker_kernel,
                             cudaFuncAttributeMaxDynamicSharedMemorySize, walkerSmem);
        cudaFuncSetAttribute(gemm_p_tc,
                             cudaFuncAttributeMaxDynamicSharedMemorySize, gemmSmem);
        configured = 1;
    }

    init_kernel<<<16, 512>>>();
    convert_kernel<<<(N_ * D_) / 256, 256>>>(a, b);
    gemm_p_tc<<<dim3(64, 64), 256, gemmSmem>>>();
    recip_kernel<<<16, 512>>>();
    w_vp_kernel<<<dim3(64, 8), 256>>>();
    prep1_kernel<<<1, 256>>>(labels);
    prep2_kernel<<<32, 256>>>(labels);
    walker_kernel<<<512, 256, walkerSmem>>>();
    finalize_kernel<<<1, 256>>>(out);
}

// round 15
// speedup vs baseline: 4.0237x; 1.8590x over previous
#include <cuda_runtime.h>
#include <cuda_bf16.h>
#include <mma.h>
#include <cstdint>

using namespace nvcuda;

#define N_ 8192
#define D_ 128
#define NLAB 10
#define SCALE 0.08838834764831845f   // 1/sqrt(128)
#define EPS 1e-8f
#define TW 128                        // walker tile width
#define KST 72                        // walker smem k-stride (64 data + 8 pad) in bf16
#define GLD 40                        // gemm smem row stride (32 data + 8 pad) in bf16
#define NCHUNK 128                    // 8192 / 64

// ---------------- scratch (device globals: allocation-free) ----------------
static __device__ __nv_bfloat16 g_E16[(size_t)N_ * N_];        // exp(p) bf16 (128 MB)
static __device__ __nv_bfloat16 g_Ws[(size_t)(N_ + TW) * N_];  // label-sorted W (+zero tail)
static __device__ __nv_bfloat16 g_ah[(size_t)N_ * D_];
static __device__ __nv_bfloat16 g_al[(size_t)N_ * D_];
static __device__ __nv_bfloat16 g_bh[(size_t)N_ * D_];
static __device__ __nv_bfloat16 g_bl[(size_t)N_ * D_];
static __device__ float g_rsum[N_];   // row sums -> rInv after recip
static __device__ float g_csum[N_];   // col sums -> cInv after recip
static __device__ float g_vp[N_];
static __device__ int   g_cnt[NLAB];
static __device__ int   g_startL[NLAB + 1];
static __device__ int   g_idx[N_];    // sorted position -> original row
static __device__ int   g_pos[N_];    // original row -> sorted position
static __device__ int   g_tilesL[NLAB];
static __device__ int   g_tileStart[NLAB + 1];
static __device__ int   g_numTiles;
static __device__ int   g_isI64;
static __device__ float g_walkerAcc;

__device__ __forceinline__ int get_label(const void* L, int i, int isI64) {
    int v = isI64 ? (int)((const long long*)L)[i] : ((const int*)L)[i];
    return min(max(v, 0), NLAB - 1);
}

__device__ __forceinline__ void cpa16(uint32_t saddr, const void* gptr) {
    asm volatile("cp.async.cg.shared.global [%0], [%1], 16;" :: "r"(saddr), "l"(gptr));
}
__device__ __forceinline__ void cpa_commit() { asm volatile("cp.async.commit_group;"); }
__device__ __forceinline__ void cpa_wait1() { asm volatile("cp.async.wait_group 1;"); }
__device__ __forceinline__ void cpa_wait0() { asm volatile("cp.async.wait_group 0;"); }

__device__ __forceinline__ void bulk128(uint32_t dst, const void* src, uint32_t mbar) {
    asm volatile(
        "cp.async.bulk.shared::cluster.global.mbarrier::complete_tx::bytes [%0], [%1], 128, [%2];"
        :: "r"(dst), "l"(src), "r"(mbar) : "memory");
}
__device__ __forceinline__ void mbar_expect(uint32_t mbar, uint32_t tx) {
    asm volatile("mbarrier.arrive.expect_tx.shared.b64 _, [%0], %1;"
                 :: "r"(mbar), "r"(tx) : "memory");
}
__device__ __forceinline__ void mbar_wait(uint32_t mbar, uint32_t parity) {
    asm volatile(
        "{\n\t.reg .pred P;\n\t"
        "WL_%=:\n\t"
        "mbarrier.try_wait.parity.acquire.cta.shared::cta.b64 P, [%0], %1, 0x989680;\n\t"
        "@P bra.uni WD_%=;\n\t"
        "bra.uni WL_%=;\n\t"
        "WD_%=:\n\t}"
        :: "r"(mbar), "r"(parity) : "memory");
}

// ---------------- 0) zero the atomic accumulators ----------------
__global__ __launch_bounds__(512) void init_kernel() {
    int i = blockIdx.x * 512 + threadIdx.x;
    if (i < N_) { g_rsum[i] = 0.f; g_csum[i] = 0.f; g_vp[i] = 0.f; }
    if (i == 0) g_walkerAcc = 0.f;
}

// ---------------- 0b) fp32 -> bf16 hi/lo split of a, b ----------------
__global__ __launch_bounds__(256) void convert_kernel(const float* __restrict__ A,
                                                      const float* __restrict__ B) {
    int i = blockIdx.x * 256 + threadIdx.x;
    float a = A[i];
    __nv_bfloat16 h = __float2bfloat16(a);
    g_ah[i] = h;
    g_al[i] = __float2bfloat16(a - __bfloat162float(h));
    float b = B[i];
    __nv_bfloat16 hb = __float2bfloat16(b);
    g_bh[i] = hb;
    g_bl[i] = __float2bfloat16(b - __bfloat162float(hb));
}

// ---------------- 1) P = a b^T * scale via split-bf16 wmma; E=exp(P); fused sums ----
__global__ __launch_bounds__(256, 2) void gemm_p_tc() {
    extern __shared__ char gsm[];
    __nv_bfloat16* sm = (__nv_bfloat16*)gsm;
    __shared__ float rs[128], cs[128];

    int tid = threadIdx.x;
    int warp = tid >> 5, lane = tid & 31;
    int wr = warp & 1;
    int wc = warp >> 1;
    int bi = blockIdx.y * 128, bj = blockIdx.x * 128;

    const int SMAT = 128 * GLD;
    uint32_t smBase = (uint32_t)__cvta_generic_to_shared(sm);

    if (tid < 128) { rs[tid] = 0.f; cs[tid] = 0.f; }

    wmma::fragment<wmma::accumulator, 16, 16, 16, float> cf[4][2];
    #pragma unroll
    for (int fi = 0; fi < 4; fi++)
        #pragma unroll
        for (int fj = 0; fj < 2; fj++) wmma::fill_fragment(cf[fi][fj], 0.f);

    auto issue = [&](int chunk, int stage) {
        int k0 = chunk * 32;
        #pragma unroll
        for (int q = 0; q < 8; q++) {
            int linear = tid + q * 256;
            int mat = linear >> 9;
            int rem = linear & 511;
            int row = rem >> 2;
            int ce = (rem & 3) * 8;
            const __nv_bfloat16* gm = (mat == 0) ? g_ah : (mat == 1) ? g_al
                                     : (mat == 2) ? g_bh : g_bl;
            int grow = ((mat < 2) ? bi : bj) + row;
            const __nv_bfloat16* src = gm + (size_t)grow * D_ + k0 + ce;
            uint32_t dst = smBase + (uint32_t)((stage * 4 + mat) * SMAT + row * GLD + ce) * 2;
            cpa16(dst, src);
        }
        cpa_commit();
    };

    issue(0, 0);
    issue(1, 1);

    for (int c = 0; c < 4; c++) {
        if (c == 3) cpa_wait0(); else cpa_wait1();
        __syncthreads();

        const __nv_bfloat16* Ah = sm + (c & 1) * 4 * SMAT;
        const __nv_bfloat16* Al = Ah + SMAT;
        const __nv_bfloat16* Bh = Ah + 2 * SMAT;
        const __nv_bfloat16* Bl = Ah + 3 * SMAT;

        #pragma unroll
        for (int ks = 0; ks < 2; ks++) {
            wmma::fragment<wmma::matrix_b, 16, 16, 16, __nv_bfloat16, wmma::col_major> bh[2], bl[2];
            #pragma unroll
            for (int j = 0; j < 2; j++) {
                wmma::load_matrix_sync(bh[j], &Bh[(wc * 32 + j * 16) * GLD + ks * 16], GLD);
                wmma::load_matrix_sync(bl[j], &Bl[(wc * 32 + j * 16) * GLD + ks * 16], GLD);
            }
            #pragma unroll
            for (int fi = 0; fi < 4; fi++) {
                wmma::fragment<wmma::matrix_a, 16, 16, 16, __nv_bfloat16, wmma::row_major> ahf, alf;
                wmma::load_matrix_sync(ahf, &Ah[(wr * 64 + fi * 16) * GLD + ks * 16], GLD);
                wmma::load_matrix_sync(alf, &Al[(wr * 64 + fi * 16) * GLD + ks * 16], GLD);
                #pragma unroll
                for (int j = 0; j < 2; j++) {
                    wmma::mma_sync(cf[fi][j], ahf, bh[j], cf[fi][j]);
                    wmma::mma_sync(cf[fi][j], ahf, bl[j], cf[fi][j]);
                    wmma::mma_sync(cf[fi][j], alf, bh[j], cf[fi][j]);
                }
            }
        }
        if (c + 2 < 4) {
            __syncthreads();
            issue(c + 2, c & 1);
        }
    }
    __syncthreads();

    float* wscr = (float*)gsm + warp * (16 * 20);
    #pragma unroll
    for (int fi = 0; fi < 4; fi++) {
        #pragma unroll
        for (int fj = 0; fj < 2; fj++) {
            #pragma unroll
            for (int e = 0; e < cf[fi][fj].num_elements; e++)
                cf[fi][fj].x[e] = __expf(cf[fi][fj].x[e] * SCALE);
            wmma::store_matrix_sync(wscr, cf[fi][fj], 20, wmma::mem_row_major);
            __syncwarp();
            if (lane < 16) {
                int r = lane;
                float vals[16], rp = 0.f;
                #pragma unroll
                for (int c2 = 0; c2 < 16; c2++) { vals[c2] = wscr[r * 20 + c2]; rp += vals[c2]; }
                uint4 p0, p1;
                __nv_bfloat162 t;
                t = __floats2bfloat162_rn(vals[0], vals[1]);   p0.x = *(unsigned*)&t;
                t = __floats2bfloat162_rn(vals[2], vals[3]);   p0.y = *(unsigned*)&t;
                t = __floats2bfloat162_rn(vals[4], vals[5]);   p0.z = *(unsigned*)&t;
                t = __floats2bfloat162_rn(vals[6], vals[7]);   p0.w = *(unsigned*)&t;
                t = __floats2bfloat162_rn(vals[8], vals[9]);   p1.x = *(unsigned*)&t;
                t = __floats2bfloat162_rn(vals[10], vals[11]); p1.y = *(unsigned*)&t;
                t = __floats2bfloat162_rn(vals[12], vals[13]); p1.z = *(unsigned*)&t;
                t = __floats2bfloat162_rn(vals[14], vals[15]); p1.w = *(unsigned*)&t;
                size_t go = (size_t)(bi + wr * 64 + fi * 16 + r) * N_ + bj + wc * 32 + fj * 16;
                *(uint4*)&g_E16[go] = p0;
                *(uint4*)&g_E16[go + 8] = p1;
                atomicAdd(&rs[wr * 64 + fi * 16 + r], rp);
            } else {
                int c2 = lane - 16;
                float cpv = 0.f;
                #pragma unroll
                for (int r = 0; r < 16; r++) cpv += wscr[r * 20 + c2];
                atomicAdd(&cs[wc * 32 + fj * 16 + c2], cpv);
            }
            __syncwarp();
        }
    }
    __syncthreads();
    if (tid < 128) atomicAdd(&g_rsum[bi + tid], rs[tid]);
    else atomicAdd(&g_csum[bj + tid - 128], cs[tid - 128]);
}

// ---------------- 2) invert sums in place ----------------
__global__ __launch_bounds__(512) void recip_kernel() {
    int i = blockIdx.x * 512 + threadIdx.x;
    if (i < N_) {
        g_rsum[i] = 1.f / g_rsum[i];
        g_csum[i] = 1.f / g_csum[i];
    }
}

// ---------------- 3) W = E * sqrt(cInv), scattered to label-sorted rows; vp ------
__global__ __launch_bounds__(256) void w_vp_kernel() {
    __shared__ float vps[128];
    int tid = threadIdx.x;
    int cg = tid & 15, rg = tid >> 4;
    int colBase = blockIdx.x * 128;
    int c = colBase + cg * 8;
    float sCI[8];
    #pragma unroll
    for (int k = 0; k < 8; k++) sCI[k] = sqrtf(g_csum[c + k]);
    float vp[8] = {};
    int r0 = blockIdx.y * 1024 + rg;
    #pragma unroll 4
    for (int it = 0; it < 64; it++) {
        int r = r0 + it * 16;
        size_t off = (size_t)r * N_ + c;
        uint4 ev = *(const uint4*)&g_E16[off];
        float rInv = g_rsum[r];
        int sr = g_pos[r];
        float e[8];
        {
            float2 f;
            f = __bfloat1622float2(*(__nv_bfloat162*)&ev.x); e[0] = f.x; e[1] = f.y;
            f = __bfloat1622float2(*(__nv_bfloat162*)&ev.y); e[2] = f.x; e[3] = f.y;
            f = __bfloat1622float2(*(__nv_bfloat162*)&ev.z); e[4] = f.x; e[5] = f.y;
            f = __bfloat1622float2(*(__nv_bfloat162*)&ev.w); e[6] = f.x; e[7] = f.y;
        }
        float w[8];
        #pragma unroll
        for (int k = 0; k < 8; k++) { w[k] = e[k] * sCI[k]; vp[k] += e[k] * rInv; }
        uint4 wp;
        __nv_bfloat162 t;
        t = __floats2bfloat162_rn(w[0], w[1]); wp.x = *(unsigned*)&t;
        t = __floats2bfloat162_rn(w[2], w[3]); wp.y = *(unsigned*)&t;
        t = __floats2bfloat162_rn(w[4], w[5]); wp.z = *(unsigned*)&t;
        t = __floats2bfloat162_rn(w[6], w[7]); wp.w = *(unsigned*)&t;
        *(uint4*)&g_Ws[(size_t)sr * N_ + c] = wp;
    }
    if (tid < 128) vps[tid] = 0.f;
    __syncthreads();
    #pragma unroll
    for (int k = 0; k < 8; k++) atomicAdd(&vps[cg * 8 + k], vp[k]);
    __syncthreads();
    if (tid < 128) atomicAdd(&g_vp[colBase + tid], vps[tid]);
}

// ---------------- 4) dtype probe + label histogram + triangular tile bookkeeping ----
__global__ __launch_bounds__(256) void prep1_kernel(const void* __restrict__ labels) {
    __shared__ int scnt[NLAB];
    __shared__ int oddNonzero;
    int tid = threadIdx.x;
    if (tid < NLAB) scnt[tid] = 0;
    if (tid == 0) oddNonzero = 0;
    __syncthreads();
    {
        const int* w = (const int*)labels;
        int local = 0;
        for (int i = tid; i < N_ / 2; i += 256)
            if (w[2 * i + 1] != 0) local = 1;
        if (local) oddNonzero = 1;
    }
    __syncthreads();
    int isI64 = !oddNonzero;
    if (tid == 0) g_isI64 = isI64;

    for (int i = tid; i < N_; i += 256)
        atomicAdd(&scnt[get_label(labels, i, isI64)], 1);
    __syncthreads();
    if (tid == 0) {
        int st = 0, ts = 0;
        for (int l = 0; l < NLAB; l++) {
            int cnum = scnt[l];
            g_cnt[l] = cnum;
            g_startL[l] = st; st += cnum;
            int tl = (cnum + TW - 1) / TW;
            g_tilesL[l] = tl;
            g_tileStart[l] = ts; ts += tl * (tl + 1) / 2;
        }
        g_startL[NLAB] = st;
        g_tileStart[NLAB] = ts;
        g_numTiles = ts;
    }
}

// ---------------- 5) stable scatter: g_idx (sorted->orig) and g_pos (orig->sorted) --
__global__ __launch_bounds__(256) void prep2_kernel(const void* __restrict__ labels) {
    __shared__ unsigned char slab[N_];
    int tid = threadIdx.x;
    int isI64 = g_isI64;
    for (int i = tid; i < N_; i += 256)
        slab[i] = (unsigned char)get_label(labels, i, isI64);
    __syncthreads();
    int i = blockIdx.x * 256 + tid;
    unsigned char lab = slab[i];
    int pos = 0;
    for (int q = 0; q < i; q++) pos += (slab[q] == lab);
    int dest = g_startL[lab] + pos;
    g_idx[dest] = i;
    g_pos[i] = dest;
}

// ---------------- 6) walker: sorted rows, cp.async.bulk + mbarrier, wmma ----------
__global__ __launch_bounds__(256) void walker_kernel() {
    extern __shared__ __align__(16) char dsm[];
    __nv_bfloat16* Us = (__nv_bfloat16*)dsm;            // 2 stages x TW x KST
    __nv_bfloat16* Vs = Us + 2 * TW * KST;
    __shared__ float rIr[TW], rIc[TW];
    __shared__ float red[8];
    __shared__ __align__(8) unsigned long long mbarArr[2];

    int tid = threadIdx.x;
    int warp = tid >> 5, lane = tid & 31;
    int wr = warp >> 1;
    int wc = warp & 1;
    int numTiles = g_numTiles;
    float blockAcc = 0.f;

    if (tid == 0) {
        asm volatile("mbarrier.init.shared.b64 [%0], 1;"
                     :: "r"((uint32_t)__cvta_generic_to_shared(&mbarArr[0])) : "memory");
        asm volatile("mbarrier.init.shared.b64 [%0], 1;"
                     :: "r"((uint32_t)__cvta_generic_to_shared(&mbarArr[1])) : "memory");
    }
    __syncthreads();
    uint32_t mb0 = (uint32_t)__cvta_generic_to_shared(&mbarArr[0]);
    uint32_t mb1 = (uint32_t)__cvta_generic_to_shared(&mbarArr[1]);
    int ph[2] = {0, 0};

    uint32_t usBase = (uint32_t)__cvta_generic_to_shared(Us);
    uint32_t vsBase = (uint32_t)__cvta_generic_to_shared(Vs);

    // this thread's copy job: one 128B row per matrix-pair per chunk
    int myRow = tid & 127;
    int myIsV = tid >> 7;                    // 0 -> U, 1 -> V
    uint32_t myDstBase = (myIsV ? vsBase : usBase) + (uint32_t)(myRow * KST) * 2;

    for (int t = blockIdx.x; t < numTiles; t += gridDim.x) {
        int L = 0;
        while (t >= g_tileStart[L + 1]) L++;
        int local = t - g_tileStart[L];
        int tl = g_tilesL[L];
        int nL = g_cnt[L];
        int base = g_startL[L];
        int ti = 0, rem = local;
        while (rem >= tl - ti) { rem -= tl - ti; ti++; }
        int tj = ti + rem;
        int offdiag = (ti != tj);

        if (tid < TW) {
            int r = ti * TW + tid;
            rIr[tid] = (r < nL) ? g_rsum[g_idx[base + r]] : 0.f;
            int c = tj * TW + tid;
            rIc[tid] = (c < nL) ? g_rsum[g_idx[base + c]] : 0.f;
        }
        wmma::fragment<wmma::accumulator, 16, 16, 16, float> cf[2][4];
        #pragma unroll
        for (int i = 0; i < 2; i++)
            #pragma unroll
            for (int j = 0; j < 4; j++) wmma::fill_fragment(cf[i][j], 0.f);
        __syncthreads();   // rIr/rIc visible; prior tile's smem reads done

        // my source row (sorted, contiguous; tail rows land in zero padding)
        int srcRow = base + (myIsV ? tj : ti) * TW + myRow;
        const __nv_bfloat16* srcBase = g_Ws + (size_t)srcRow * N_;

        // prologue: chunks 0 and 1
        #pragma unroll
        for (int pc = 0; pc < 2; pc++) {
            if (tid == 0) mbar_expect(pc ? mb1 : mb0, 32768);
            bulk128(myDstBase + (uint32_t)(pc * TW * KST) * 2,
                    srcBase + pc * 64, pc ? mb1 : mb0);
        }

        for (int c = 0; c < NCHUNK; c++) {
            int s = c & 1;
            uint32_t mb = s ? mb1 : mb0;
            mbar_wait(mb, ph[s] & 1);
            ph[s]++;

            const __nv_bfloat16* Uc = Us + s * TW * KST;
            const __nv_bfloat16* Vc = Vs + s * TW * KST;
            #pragma unroll
            for (int ks = 0; ks < 4; ks++) {
                wmma::fragment<wmma::matrix_a, 16, 16, 16, __nv_bfloat16, wmma::row_major> a0, a1;
                wmma::load_matrix_sync(a0, &Uc[(wr * 32) * KST + ks * 16], KST);
                wmma::load_matrix_sync(a1, &Uc[(wr * 32 + 16) * KST + ks * 16], KST);
                #pragma unroll
                for (int j = 0; j < 4; j++) {
                    wmma::fragment<wmma::matrix_b, 16, 16, 16, __nv_bfloat16, wmma::col_major> b;
                    wmma::load_matrix_sync(b, &Vc[(wc * 64 + j * 16) * KST + ks * 16], KST);
                    wmma::mma_sync(cf[0][j], a0, b, cf[0][j]);
                    wmma::mma_sync(cf[1][j], a1, b, cf[1][j]);
                }
            }
            __syncthreads();    // all warps done with stage s
            if (c + 2 < NCHUNK) {
                if (tid == 0) mbar_expect(mb, 32768);
                bulk128(myDstBase + (uint32_t)(s * TW * KST) * 2,
                        srcBase + (c + 2) * 64, mb);
            }
        }

        // epilogue: S tile -> both orientations' log contributions
        float* wscr = (float*)dsm + warp * 256;
        int rlim = nL - ti * TW;
        int clim = nL - tj * TW;
        float s = 0.f;
        #pragma unroll
        for (int i2 = 0; i2 < 2; i2++)
            #pragma unroll
            for (int j4 = 0; j4 < 4; j4++) {
                wmma::store_matrix_sync(wscr, cf[i2][j4], 16, wmma::mem_row_major);
                __syncwarp();
                #pragma unroll
                for (int q = 0; q < 8; q++) {
                    int idx = lane + q * 32;
                    int lr = wr * 32 + i2 * 16 + (idx >> 4);
                    int lc = wc * 64 + j4 * 16 + (idx & 15);
                    if (lr < rlim && lc < clim) {
                        float sv = wscr[idx];
                        s += __logf(EPS + rIr[lr] * sv);
                        if (offdiag) s += __logf(EPS + rIc[lc] * sv);
                    }
                }
                __syncwarp();
            }
        #pragma unroll
        for (int o = 16; o; o >>= 1) s += __shfl_xor_sync(~0u, s, o);
        if (lane == 0) red[warp] = s;
        __syncthreads();
        if (tid == 0) {
            float ts = 0.f;
            for (int w = 0; w < 8; w++) ts += red[w];
            blockAcc += ts / (float)nL;
        }
        __syncthreads();
    }
    if (tid == 0) atomicAdd(&g_walkerAcc, blockAcc);
}

// ---------------- 7) visit loss + outputs ----------------
__global__ __launch_bounds__(256) void finalize_kernel(float* __restrict__ out) {
    __shared__ float red[8];
    int tid = threadIdx.x;
    float s = 0.f;
    for (int m = tid; m < N_; m += 256)
        s += logf(EPS + g_vp[m] * (1.0f / N_));
    #pragma unroll
    for (int o = 16; o; o >>= 1) s += __shfl_xor_sync(~0u, s, o);
    if ((tid & 31) == 0) red[tid >> 5] = s;
    __syncthreads();
    if (tid == 0) {
        float t = 0.f;
        for (int w = 0; w < 8; w++) t += red[w];
        out[1] = -t * (1.0f / N_);              // visit_loss
        out[0] = -g_walkerAcc * (1.0f / N_);    // walker_loss
    }
}

// ---------------- launch ----------------
extern "C" void kernel_launch(void* const* d_in, const int* in_sizes, int n_in,
                              void* d_out, int out_size) {
    const float* a = (const float*)d_in[0];
    const float* b = (const float*)d_in[1];
    const void* labels = d_in[2];
    float* out = (float*)d_out;

    const int walkerSmem = 4 * TW * KST * 2;     // 73728 bytes
    const int gemmSmem = 2 * 4 * 128 * GLD * 2;  // 81920 bytes
    static int configured = 0;
    if (!configured) {
        cudaFuncSetAttribute(walker_kernel,
                             cudaFuncAttributeMaxDynamicSharedMemorySize, walkerSmem);
        cudaFuncSetAttribute(gemm_p_tc,
                             cudaFuncAttributeMaxDynamicSharedMemorySize, gemmSmem);
        configured = 1;
    }

    init_kernel<<<16, 512>>>();
    prep1_kernel<<<1, 256>>>(labels);
    prep2_kernel<<<32, 256>>>(labels);
    convert_kernel<<<(N_ * D_) / 256, 256>>>(a, b);
    gemm_p_tc<<<dim3(64, 64), 256, gemmSmem>>>();
    recip_kernel<<<16, 512>>>();
    w_vp_kernel<<<dim3(64, 8), 256>>>();
    walker_kernel<<<512, 256, walkerSmem>>>();
    finalize_kernel<<<1, 256>>>(out);
}